// round 4
// baseline (speedup 1.0000x reference)
#include <cuda_runtime.h>
#include <cuda_bf16.h>
#include <math.h>
#include <stdint.h>

#define BATCH 8192

// Scratch (device globals) — activations stored as bf16 hi/lo pairs
__device__ __nv_bfloat16 g_a1h[BATCH * 3136];
__device__ __nv_bfloat16 g_a1l[BATCH * 3136];
__device__ __nv_bfloat16 g_a2h[BATCH * 1568];  // [b][px*32+ic]
__device__ __nv_bfloat16 g_a2l[BATCH * 1568];
__device__ __nv_bfloat16 g_a3h[BATCH * 1024];
__device__ __nv_bfloat16 g_a3l[BATCH * 1024];
__device__ float g_a4[BATCH * 256];
__device__ __nv_bfloat16 g_fw1h[256 * 1024];
__device__ __nv_bfloat16 g_fw1l[256 * 1024];

__device__ __forceinline__ void bf16split(float v, __nv_bfloat16& h, __nv_bfloat16& l) {
    h = __float2bfloat16(v);
    l = __float2bfloat16(v - __bfloat162float(h));
}

__device__ __forceinline__ void mma_bf16(float* c,
                                         uint32_t a0, uint32_t a1, uint32_t a2, uint32_t a3,
                                         uint32_t b0, uint32_t b1) {
    asm volatile(
        "mma.sync.aligned.m16n8k16.row.col.f32.bf16.bf16.f32 "
        "{%0,%1,%2,%3}, {%4,%5,%6,%7}, {%8,%9}, {%0,%1,%2,%3};"
        : "+f"(c[0]), "+f"(c[1]), "+f"(c[2]), "+f"(c[3])
        : "r"(a0), "r"(a1), "r"(a2), "r"(a3), "r"(b0), "r"(b1));
}

__device__ __forceinline__ uint32_t lds_u32(const __nv_bfloat16* p, int elem_idx) {
    return *reinterpret_cast<const uint32_t*>(p + elem_idx);
}

// ---------------- k_prep: split fc1 weights ----------------
__global__ void __launch_bounds__(256) k_prep(const float* __restrict__ fw1) {
    int i = blockIdx.x * 256 + threadIdx.x;
    float v = fw1[i];
    __nv_bfloat16 h, l;
    bf16split(v, h, l);
    g_fw1h[i] = h; g_fw1l[i] = l;
}

// ---------------- conv1 (1->16) FFMA + relu + pool ----------------
__global__ void __launch_bounds__(224) k_conv1(const float* __restrict__ x,
                                               const float* __restrict__ w1,
                                               const float* __restrict__ b1) {
    __shared__ float s_in[32 * 33];
    __shared__ float s_w[400];
    __shared__ float s_b[16];
    const int img = blockIdx.x;
    const int tid = threadIdx.x;

    for (int i = tid; i < 32 * 33; i += 224) s_in[i] = 0.f;
    for (int i = tid; i < 400; i += 224) s_w[i] = w1[i];
    if (tid < 16) s_b[tid] = b1[tid];
    __syncthreads();
    const float* xin = x + img * 784;
    for (int i = tid; i < 784; i += 224) {
        int r = i / 28, c = i - r * 28;
        s_in[(r + 2) * 33 + (c + 2)] = xin[i];
    }
    __syncthreads();

    if (tid < 196) {
        int py = tid / 14, px = tid - py * 14;
        int y0 = 2 * py, x0 = 2 * px;
        float acc[16][4];
#pragma unroll
        for (int j = 0; j < 16; j++) {
            float bv = s_b[j];
            acc[j][0] = bv; acc[j][1] = bv; acc[j][2] = bv; acc[j][3] = bv;
        }
#pragma unroll
        for (int ky = 0; ky < 5; ky++) {
            const float* r0 = &s_in[(y0 + ky) * 33 + x0];
            const float* r1 = r0 + 33;
#pragma unroll
            for (int kx = 0; kx < 5; kx++) {
                float i0 = r0[kx], i1 = r0[kx + 1], i2 = r1[kx], i3 = r1[kx + 1];
#pragma unroll
                for (int j = 0; j < 16; j++) {
                    float wv = s_w[j * 25 + ky * 5 + kx];
                    acc[j][0] += wv * i0; acc[j][1] += wv * i1;
                    acc[j][2] += wv * i2; acc[j][3] += wv * i3;
                }
            }
        }
        int dbase = img * 3136 + py * 14 + px;
#pragma unroll
        for (int j = 0; j < 16; j++) {
            float m = fmaxf(fmaxf(acc[j][0], acc[j][1]), fmaxf(acc[j][2], acc[j][3]));
            m = fmaxf(m, 0.f);
            __nv_bfloat16 h, l;
            bf16split(m, h, l);
            g_a1h[dbase + j * 196] = h;
            g_a1l[dbase + j * 196] = l;
        }
    }
}

// ---------------- conv2 (16->32) bf16x3 MMA, 512 thr, conflict-free strides ----------------
// input stride 24 elem (48B), weight stride 408 elem (816B≡48B mod128) — conflict-free
// SMEM: inh 32832 | inl 32832 | wh 26112 | wl 26112 | pool 12544 | bias 128 = 130560
#define C2_SMEM 130560
__global__ void __launch_bounds__(512, 1) k_conv2(const float* __restrict__ w2,
                                                  const float* __restrict__ b2) {
    extern __shared__ char smem[];
    __nv_bfloat16* s_inh = (__nv_bfloat16*)(smem);              // 2*8208 elem
    __nv_bfloat16* s_inl = (__nv_bfloat16*)(smem + 32832);
    __nv_bfloat16* s_wh  = (__nv_bfloat16*)(smem + 65664);      // 32*408
    __nv_bfloat16* s_wl  = (__nv_bfloat16*)(smem + 91776);
    int*           s_pool = (int*)(smem + 117888);              // 2*49*32
    float*         s_bias = (float*)(smem + 130432);

    const int img0 = blockIdx.x * 2;
    const int tid = threadIdx.x;
    const int warp = tid >> 5;
    const int lane = tid & 31;
    const int gid = lane >> 2;
    const int tg  = lane & 3;
    const int kk  = tg * 2;

    uint32_t* zin = (uint32_t*)smem;
    for (int i = tid; i < 16416; i += 512) zin[i] = 0u;
    for (int i = tid; i < 3136; i += 512) s_pool[i] = 0;
    if (tid < 32) s_bias[tid] = b2[tid];
    for (int i = tid; i < 12800; i += 512) {
        int oc = i / 400, r = i - oc * 400;
        int ic = r / 25, off = r - ic * 25;
        __nv_bfloat16 h, l;
        bf16split(w2[i], h, l);
        int d = oc * 408 + off * 16 + ic;
        s_wh[d] = h; s_wl[d] = l;
    }
    __syncthreads();
    for (int i = tid; i < 6272; i += 512) {
        int img = i / 3136, idx = i - img * 3136;
        int ic = idx / 196, p = idx - ic * 196;
        int r = p / 14, c = p - r * 14;
        int src = (img0 + img) * 3136 + idx;
        int d = img * 8208 + ((r + 2) * 19 + (c + 2)) * 24 + ic;
        s_inh[d] = g_a1h[src];
        s_inl[d] = g_a1l[src];
    }
    __syncthreads();

    // 26 m-tiles over 16 warps: t = warp, warp+16
    int aoff0[2], aoff1[2];
#pragma unroll
    for (int ti = 0; ti < 2; ti++) {
        int t = warp + 16 * ti;
        if (t < 26) {
            int img = t / 13, base = (t - img * 13) * 16;
            int p0 = base + gid; if (p0 > 195) p0 = 195;
            int p1 = base + gid + 8; if (p1 > 195) p1 = 195;
            int y0 = p0 / 14, x0 = p0 - y0 * 14;
            int y1 = p1 / 14, x1 = p1 - y1 * 14;
            aoff0[ti] = img * 8208 + (y0 * 19 + x0) * 24;
            aoff1[ti] = img * 8208 + (y1 * 19 + x1) * 24;
        }
    }

    float acc[2][4][4];
#pragma unroll
    for (int ti = 0; ti < 2; ti++)
#pragma unroll
        for (int nt = 0; nt < 4; nt++)
#pragma unroll
            for (int j = 0; j < 4; j++) acc[ti][nt][j] = 0.f;

#pragma unroll 1
    for (int off = 0; off < 25; off++) {
        int dy = off / 5, dx = off - dy * 5;
        int dbase = (dy * 19 + dx) * 24 + kk;
        uint32_t bh0[4], bh1[4], bl0[4], bl1[4];
#pragma unroll
        for (int nt = 0; nt < 4; nt++) {
            int wr = (nt * 8 + gid) * 408 + off * 16 + kk;
            bh0[nt] = lds_u32(s_wh, wr); bh1[nt] = lds_u32(s_wh, wr + 8);
            bl0[nt] = lds_u32(s_wl, wr); bl1[nt] = lds_u32(s_wl, wr + 8);
        }
#pragma unroll
        for (int ti = 0; ti < 2; ti++) {
            int t = warp + 16 * ti;
            if (t < 26) {
                int o0 = aoff0[ti] + dbase;
                int o1 = aoff1[ti] + dbase;
                uint32_t ah0 = lds_u32(s_inh, o0), ah1 = lds_u32(s_inh, o1);
                uint32_t ah2 = lds_u32(s_inh, o0 + 8), ah3 = lds_u32(s_inh, o1 + 8);
                uint32_t al0 = lds_u32(s_inl, o0), al1 = lds_u32(s_inl, o1);
                uint32_t al2 = lds_u32(s_inl, o0 + 8), al3 = lds_u32(s_inl, o1 + 8);
#pragma unroll
                for (int nt = 0; nt < 4; nt++)
                    mma_bf16(acc[ti][nt], ah0, ah1, ah2, ah3, bh0[nt], bh1[nt]);
#pragma unroll
                for (int nt = 0; nt < 4; nt++)
                    mma_bf16(acc[ti][nt], ah0, ah1, ah2, ah3, bl0[nt], bl1[nt]);
#pragma unroll
                for (int nt = 0; nt < 4; nt++)
                    mma_bf16(acc[ti][nt], al0, al1, al2, al3, bh0[nt], bh1[nt]);
            }
        }
    }

#pragma unroll
    for (int ti = 0; ti < 2; ti++) {
        int t = warp + 16 * ti;
        if (t < 26) {
            int img = t / 13, base = (t - img * 13) * 16;
            int p0 = base + gid, p1 = p0 + 8;
#pragma unroll
            for (int nt = 0; nt < 4; nt++) {
                int col = nt * 8 + kk;
                float bb0 = s_bias[col], bb1 = s_bias[col + 1];
                if (p0 < 196) {
                    int y = p0 / 14, x = p0 - y * 14;
                    int pi = img * 1568 + ((y >> 1) * 7 + (x >> 1)) * 32;
                    atomicMax(&s_pool[pi + col], __float_as_int(fmaxf(acc[ti][nt][0] + bb0, 0.f)));
                    atomicMax(&s_pool[pi + col + 1], __float_as_int(fmaxf(acc[ti][nt][1] + bb1, 0.f)));
                }
                if (p1 < 196) {
                    int y = p1 / 14, x = p1 - y * 14;
                    int pi = img * 1568 + ((y >> 1) * 7 + (x >> 1)) * 32;
                    atomicMax(&s_pool[pi + col], __float_as_int(fmaxf(acc[ti][nt][2] + bb0, 0.f)));
                    atomicMax(&s_pool[pi + col + 1], __float_as_int(fmaxf(acc[ti][nt][3] + bb1, 0.f)));
                }
            }
        }
    }
    __syncthreads();
    for (int j = tid; j < 3136; j += 512) {
        int img = j / 1568, rem = j - img * 1568;
        float v = __int_as_float(s_pool[j]);
        __nv_bfloat16 h, l;
        bf16split(v, h, l);
        int dst = (img0 + img) * 1568 + rem;
        g_a2h[dst] = h; g_a2l[dst] = l;
    }
}

// ---------------- conv3 (32->64) bf16x3 MMA, 512 thr, conflict-free strides ----------------
// input stride 40 elem (80B), weight stride 808 elem (1616B≡80B mod128) — conflict-free
// SMEM: inh 42240 | inl 42240 | wh 51712 | wl 51712 | pool 8192 | bias 128 = 196224
#define C3_SMEM 196224
__global__ void __launch_bounds__(512, 1) k_conv3(const float* __restrict__ w3,
                                                  const float* __restrict__ b3) {
    extern __shared__ char smem[];
    __nv_bfloat16* s_inh = (__nv_bfloat16*)(smem);              // 4*5280 elem
    __nv_bfloat16* s_inl = (__nv_bfloat16*)(smem + 42240);
    __nv_bfloat16* s_wh  = (__nv_bfloat16*)(smem + 84480);      // 32*808
    __nv_bfloat16* s_wl  = (__nv_bfloat16*)(smem + 136192);
    int*           s_pool = (int*)(smem + 187904);              // 4*16*32
    float*         s_bias = (float*)(smem + 196096);

    const int img0 = blockIdx.x * 4;
    const int g = blockIdx.y;        // oc-group: 0 or 1
    const int tid = threadIdx.x;
    const int warp = tid >> 5;       // 0..15 = m-tile
    const int lane = tid & 31;
    const int gid = lane >> 2;
    const int tg  = lane & 3;
    const int kk  = tg * 2;

    uint32_t* zin = (uint32_t*)smem;
    for (int i = tid; i < 21120; i += 512) zin[i] = 0u;
    for (int i = tid; i < 2048; i += 512) s_pool[i] = 0;
    if (tid < 32) s_bias[tid] = b3[g * 32 + tid];
    const float* wg = w3 + g * 32 * 800;
    for (int i = tid; i < 25600; i += 512) {
        int ocl = i / 800, r = i - ocl * 800;
        int ic = r / 25, off = r - ic * 25;
        __nv_bfloat16 h, l;
        bf16split(wg[i], h, l);
        int d = ocl * 808 + off * 32 + ic;
        s_wh[d] = h; s_wl[d] = l;
    }
    __syncthreads();
    for (int i = tid; i < 6272; i += 512) {
        int img = i / 1568, rem = i - img * 1568;
        int p = rem / 32, ic = rem - p * 32;
        int y = p / 7, x = p - y * 7;
        int src = (img0 + img) * 1568 + rem;
        int d = img * 5280 + ((y + 2) * 12 + (x + 2)) * 40 + ic;
        s_inh[d] = g_a2h[src];
        s_inl[d] = g_a2l[src];
    }
    __syncthreads();

    // 16 m-tiles, one per warp
    const int timg = warp >> 2, base = (warp & 3) * 16;
    int p0 = base + gid; if (p0 > 48) p0 = 48;
    int p1 = base + gid + 8; if (p1 > 48) p1 = 48;
    int y0 = p0 / 7, x0 = p0 - y0 * 7;
    int y1 = p1 / 7, x1 = p1 - y1 * 7;
    const int aoff0 = timg * 5280 + (y0 * 12 + x0) * 40;
    const int aoff1 = timg * 5280 + (y1 * 12 + x1) * 40;

    float acc[4][4];
#pragma unroll
    for (int nt = 0; nt < 4; nt++)
#pragma unroll
        for (int j = 0; j < 4; j++) acc[nt][j] = 0.f;

#pragma unroll 1
    for (int s = 0; s < 50; s++) {
        int off = s >> 1;
        int ich = (s & 1) * 16;
        int dy = off / 5, dx = off - dy * 5;
        int dbase = (dy * 12 + dx) * 40 + ich + kk;
        uint32_t bh0[4], bh1[4], bl0[4], bl1[4];
#pragma unroll
        for (int nt = 0; nt < 4; nt++) {
            int wr = (nt * 8 + gid) * 808 + off * 32 + ich + kk;
            bh0[nt] = lds_u32(s_wh, wr); bh1[nt] = lds_u32(s_wh, wr + 8);
            bl0[nt] = lds_u32(s_wl, wr); bl1[nt] = lds_u32(s_wl, wr + 8);
        }
        int o0 = aoff0 + dbase;
        int o1 = aoff1 + dbase;
        uint32_t ah0 = lds_u32(s_inh, o0), ah1 = lds_u32(s_inh, o1);
        uint32_t ah2 = lds_u32(s_inh, o0 + 8), ah3 = lds_u32(s_inh, o1 + 8);
        uint32_t al0 = lds_u32(s_inl, o0), al1 = lds_u32(s_inl, o1);
        uint32_t al2 = lds_u32(s_inl, o0 + 8), al3 = lds_u32(s_inl, o1 + 8);
#pragma unroll
        for (int nt = 0; nt < 4; nt++)
            mma_bf16(acc[nt], ah0, ah1, ah2, ah3, bh0[nt], bh1[nt]);
#pragma unroll
        for (int nt = 0; nt < 4; nt++)
            mma_bf16(acc[nt], ah0, ah1, ah2, ah3, bl0[nt], bl1[nt]);
#pragma unroll
        for (int nt = 0; nt < 4; nt++)
            mma_bf16(acc[nt], al0, al1, al2, al3, bh0[nt], bh1[nt]);
    }

    // epilogue: bias + relu, fused pool (pad=1)
    {
        int q0 = base + gid, q1 = q0 + 8;
#pragma unroll
        for (int nt = 0; nt < 4; nt++) {
            int col = nt * 8 + kk;
            float bb0 = s_bias[col], bb1 = s_bias[col + 1];
            if (q0 < 49) {
                int y = q0 / 7, x = q0 - y * 7;
                int pi = timg * 512 + (((y + 1) >> 1) * 4 + ((x + 1) >> 1)) * 32;
                atomicMax(&s_pool[pi + col], __float_as_int(fmaxf(acc[nt][0] + bb0, 0.f)));
                atomicMax(&s_pool[pi + col + 1], __float_as_int(fmaxf(acc[nt][1] + bb1, 0.f)));
            }
            if (q1 < 49) {
                int y = q1 / 7, x = q1 - y * 7;
                int pi = timg * 512 + (((y + 1) >> 1) * 4 + ((x + 1) >> 1)) * 32;
                atomicMax(&s_pool[pi + col], __float_as_int(fmaxf(acc[nt][2] + bb0, 0.f)));
                atomicMax(&s_pool[pi + col + 1], __float_as_int(fmaxf(acc[nt][3] + bb1, 0.f)));
            }
        }
    }
    __syncthreads();
    for (int j = tid; j < 2048; j += 512) {
        int img = j >> 9, rem = j & 511;
        int pidx = rem >> 5, ocl = rem & 31;
        float v = __int_as_float(s_pool[j]);
        __nv_bfloat16 h, l;
        bf16split(v, h, l);
        int dst = (img0 + img) * 1024 + (g * 32 + ocl) * 16 + pidx;
        g_a3h[dst] = h; g_a3l[dst] = l;
    }
}

// ---------------- fc1 via bf16x3 MMA ----------------
#define FC1_STRIDE 72
#define FC1_SMEM (4 * 128 * FC1_STRIDE * 2)
__global__ void __launch_bounds__(256) k_fc1(const float* __restrict__ bias) {
    extern __shared__ char smem[];
    __nv_bfloat16* s_ah = (__nv_bfloat16*)smem;
    __nv_bfloat16* s_al = s_ah + 128 * FC1_STRIDE;
    __nv_bfloat16* s_bh = s_al + 128 * FC1_STRIDE;
    __nv_bfloat16* s_bl = s_bh + 128 * FC1_STRIDE;
    const int tid = threadIdx.x;
    const int warp = tid >> 5, lane = tid & 31;
    const int wm = warp >> 1, wn = warp & 1;
    const int m0 = blockIdx.y * 128, n0 = blockIdx.x * 128;
    const int gid = lane >> 2, tg = lane & 3;

    float acc[2][8][4];
#pragma unroll
    for (int mt = 0; mt < 2; mt++)
#pragma unroll
        for (int nt = 0; nt < 8; nt++)
#pragma unroll
            for (int j = 0; j < 4; j++) acc[mt][nt][j] = 0.f;

#pragma unroll 1
    for (int k0 = 0; k0 < 1024; k0 += 64) {
        __syncthreads();
        for (int i = tid; i < 2048; i += 256) {
            int j = i & 1023;
            int row = j >> 3, koct = j & 7;
            int eoff = row * FC1_STRIDE + koct * 8;
            int gsrc = row * 1024 + k0 + koct * 8;
            if (i < 1024) {
                *(uint4*)(s_ah + eoff) = *(const uint4*)(g_a3h + (m0 * 1024) + gsrc);
                *(uint4*)(s_al + eoff) = *(const uint4*)(g_a3l + (m0 * 1024) + gsrc);
            } else {
                *(uint4*)(s_bh + eoff) = *(const uint4*)(g_fw1h + (n0 * 1024) + gsrc);
                *(uint4*)(s_bl + eoff) = *(const uint4*)(g_fw1l + (n0 * 1024) + gsrc);
            }
        }
        __syncthreads();
#pragma unroll
        for (int ks = 0; ks < 4; ks++) {
            int kb = ks * 16 + tg * 2;
            uint32_t ah[2][4], al[2][4];
#pragma unroll
            for (int mt = 0; mt < 2; mt++) {
                int base = (wm * 32 + mt * 16 + gid) * FC1_STRIDE + kb;
                ah[mt][0] = lds_u32(s_ah, base);
                ah[mt][1] = lds_u32(s_ah, base + 8 * FC1_STRIDE);
                ah[mt][2] = lds_u32(s_ah, base + 8);
                ah[mt][3] = lds_u32(s_ah, base + 8 * FC1_STRIDE + 8);
                al[mt][0] = lds_u32(s_al, base);
                al[mt][1] = lds_u32(s_al, base + 8 * FC1_STRIDE);
                al[mt][2] = lds_u32(s_al, base + 8);
                al[mt][3] = lds_u32(s_al, base + 8 * FC1_STRIDE + 8);
            }
            uint32_t bh[8][2], bl[8][2];
#pragma unroll
            for (int nt = 0; nt < 8; nt++) {
                int base = (wn * 64 + nt * 8 + gid) * FC1_STRIDE + kb;
                bh[nt][0] = lds_u32(s_bh, base); bh[nt][1] = lds_u32(s_bh, base + 8);
                bl[nt][0] = lds_u32(s_bl, base); bl[nt][1] = lds_u32(s_bl, base + 8);
            }
#pragma unroll
            for (int mt = 0; mt < 2; mt++) {
#pragma unroll
                for (int nt = 0; nt < 8; nt++)
                    mma_bf16(acc[mt][nt], ah[mt][0], ah[mt][1], ah[mt][2], ah[mt][3], bh[nt][0], bh[nt][1]);
#pragma unroll
                for (int nt = 0; nt < 8; nt++)
                    mma_bf16(acc[mt][nt], ah[mt][0], ah[mt][1], ah[mt][2], ah[mt][3], bl[nt][0], bl[nt][1]);
#pragma unroll
                for (int nt = 0; nt < 8; nt++)
                    mma_bf16(acc[mt][nt], al[mt][0], al[mt][1], al[mt][2], al[mt][3], bh[nt][0], bh[nt][1]);
            }
        }
    }
#pragma unroll
    for (int mt = 0; mt < 2; mt++) {
        int r = m0 + wm * 32 + mt * 16 + gid;
#pragma unroll
        for (int nt = 0; nt < 8; nt++) {
            int c = n0 + wn * 64 + nt * 8 + tg * 2;
            float b0 = bias[c], b1 = bias[c + 1];
            g_a4[r * 256 + c]           = fmaxf(acc[mt][nt][0] + b0, 0.f);
            g_a4[r * 256 + c + 1]       = fmaxf(acc[mt][nt][1] + b1, 0.f);
            g_a4[(r + 8) * 256 + c]     = fmaxf(acc[mt][nt][2] + b0, 0.f);
            g_a4[(r + 8) * 256 + c + 1] = fmaxf(acc[mt][nt][3] + b1, 0.f);
        }
    }
}

// ---------------- fc2 + log_softmax ----------------
__global__ void __launch_bounds__(256) k_fc2(const float* __restrict__ W,
                                             const float* __restrict__ bias,
                                             float* __restrict__ out) {
    __shared__ float s_w[2560];
    __shared__ float s_b[10];
    const int tid = threadIdx.x;
    for (int i = tid; i < 2560; i += 256) s_w[i] = W[i];
    if (tid < 10) s_b[tid] = bias[tid];
    __syncthreads();

    const int warp = tid >> 5, lane = tid & 31;
    const int row = blockIdx.x * 8 + warp;
    float hv[8];
    const float* hp = g_a4 + row * 256 + lane;
#pragma unroll
    for (int j = 0; j < 8; j++) hv[j] = hp[j * 32];

    float acc[10];
#pragma unroll
    for (int o = 0; o < 10; o++) acc[o] = 0.f;
#pragma unroll
    for (int j = 0; j < 8; j++) {
#pragma unroll
        for (int o = 0; o < 10; o++)
            acc[o] += hv[j] * s_w[o * 256 + lane + j * 32];
    }
#pragma unroll
    for (int o = 0; o < 10; o++) {
#pragma unroll
        for (int off = 16; off > 0; off >>= 1)
            acc[o] += __shfl_xor_sync(0xffffffffu, acc[o], off);
    }
    if (lane == 0) {
        float l[10], m = -1e30f;
#pragma unroll
        for (int o = 0; o < 10; o++) { l[o] = acc[o] + s_b[o]; m = fmaxf(m, l[o]); }
        float s = 0.f;
#pragma unroll
        for (int o = 0; o < 10; o++) s += expf(l[o] - m);
        float ls = logf(s);
        float* op = out + row * 10;
#pragma unroll
        for (int o = 0; o < 10; o++) op[o] = l[o] - m - ls;
    }
}

extern "C" void kernel_launch(void* const* d_in, const int* in_sizes, int n_in,
                              void* d_out, int out_size) {
    const float* x   = (const float*)d_in[0];
    const float* w1  = (const float*)d_in[1];
    const float* b1  = (const float*)d_in[2];
    const float* w2  = (const float*)d_in[3];
    const float* b2  = (const float*)d_in[4];
    const float* w3  = (const float*)d_in[5];
    const float* b3  = (const float*)d_in[6];
    const float* fw1 = (const float*)d_in[7];
    const float* fb1 = (const float*)d_in[8];
    const float* fw2 = (const float*)d_in[9];
    const float* fb2 = (const float*)d_in[10];
    float* out = (float*)d_out;

    cudaFuncSetAttribute(k_conv2, cudaFuncAttributeMaxDynamicSharedMemorySize, C2_SMEM);
    cudaFuncSetAttribute(k_conv3, cudaFuncAttributeMaxDynamicSharedMemorySize, C3_SMEM);
    cudaFuncSetAttribute(k_fc1,   cudaFuncAttributeMaxDynamicSharedMemorySize, FC1_SMEM);

    k_prep<<<1024, 256>>>(fw1);
    k_conv1<<<BATCH, 224>>>(x, w1, b1);
    k_conv2<<<BATCH / 2, 512, C2_SMEM>>>(w2, b2);
    k_conv3<<<dim3(BATCH / 4, 2), 512, C3_SMEM>>>(w3, b3);
    k_fc1<<<dim3(2, BATCH / 128), 256, FC1_SMEM>>>(fb1);
    k_fc2<<<BATCH / 8, 256>>>(fw2, fb2, out);
}

// round 5
// speedup vs baseline: 1.1559x; 1.1559x over previous
#include <cuda_runtime.h>
#include <cuda_bf16.h>
#include <math.h>
#include <stdint.h>

#define BATCH 8192

// Activations / weights in gmem, bf16 hi/lo interleaved in groups of 4:
//   group p (4 elems): [hi(2p), hi(2p+1), lo(2p), lo(2p+1)]
__device__ __nv_bfloat16 g_a1[BATCH * 196 * 32];   // conv1 out: [b][px][16ic -> 32 elem]
__device__ __nv_bfloat16 g_a2[BATCH * 49 * 64];    // conv2 out: [b][px][32ic -> 64 elem]
__device__ __nv_bfloat16 g_a3[BATCH * 2048];       // conv3 out: [b][1024k -> 2048 elem]
__device__ float g_a4[BATCH * 256];                // fc1 out
__device__ __nv_bfloat16 g_fw1[256 * 2048];        // fc1 W interleaved
__device__ __nv_bfloat16 g_w2i[32 * 800];          // conv2 W: [oc][off*32 + p*4]
__device__ __nv_bfloat16 g_w3i[64 * 1600];         // conv3 W: [oc][off*64 + p*4]

__device__ __forceinline__ uint16_t bfbits(__nv_bfloat16 x) {
    return *reinterpret_cast<uint16_t*>(&x);
}
__device__ __forceinline__ void bf16split(float v, __nv_bfloat16& h, __nv_bfloat16& l) {
    h = __float2bfloat16(v);
    l = __float2bfloat16(v - __bfloat162float(h));
}
// pack two floats into an interleaved 4-elem group (8 bytes)
__device__ __forceinline__ uint2 pack4(float v0, float v1) {
    __nv_bfloat16 h0, l0, h1, l1;
    bf16split(v0, h0, l0);
    bf16split(v1, h1, l1);
    uint2 r;
    r.x = (uint32_t)bfbits(h0) | ((uint32_t)bfbits(h1) << 16);
    r.y = (uint32_t)bfbits(l0) | ((uint32_t)bfbits(l1) << 16);
    return r;
}

__device__ __forceinline__ void mma_bf16(float* c,
                                         uint32_t a0, uint32_t a1, uint32_t a2, uint32_t a3,
                                         uint32_t b0, uint32_t b1) {
    asm volatile(
        "mma.sync.aligned.m16n8k16.row.col.f32.bf16.bf16.f32 "
        "{%0,%1,%2,%3}, {%4,%5,%6,%7}, {%8,%9}, {%0,%1,%2,%3};"
        : "+f"(c[0]), "+f"(c[1]), "+f"(c[2]), "+f"(c[3])
        : "r"(a0), "r"(a1), "r"(a2), "r"(a3), "r"(b0), "r"(b1));
}

__device__ __forceinline__ uint2 lds_u64(const __nv_bfloat16* p, int elem_idx) {
    return *reinterpret_cast<const uint2*>(p + elem_idx);
}

// ---------------- prep kernels: interleave weights in gmem ----------------
__global__ void __launch_bounds__(256) k_prep_fc1(const float* __restrict__ fw1) {
    int i = blockIdx.x * 256 + threadIdx.x;            // 131072 = 256 rows * 512 pairs
    int row = i >> 9, p = i & 511;
    uint2 v = pack4(fw1[row * 1024 + 2 * p], fw1[row * 1024 + 2 * p + 1]);
    *reinterpret_cast<uint2*>(g_fw1 + row * 2048 + p * 4) = v;
}
__global__ void __launch_bounds__(256) k_prep_w2(const float* __restrict__ w2) {
    int i = blockIdx.x * 256 + threadIdx.x;            // 6400 = 32 oc * 25 off * 8 p
    if (i >= 6400) return;
    int oc = i / 200, r = i - oc * 200;
    int off = r >> 3, p = r & 7;
    uint2 v = pack4(w2[oc * 400 + (2 * p) * 25 + off], w2[oc * 400 + (2 * p + 1) * 25 + off]);
    *reinterpret_cast<uint2*>(g_w2i + oc * 800 + off * 32 + p * 4) = v;
}
__global__ void __launch_bounds__(256) k_prep_w3(const float* __restrict__ w3) {
    int i = blockIdx.x * 256 + threadIdx.x;            // 25600 = 64 oc * 25 off * 16 p
    int oc = i / 400, r = i - oc * 400;
    int off = r >> 4, p = r & 15;
    uint2 v = pack4(w3[oc * 800 + (2 * p) * 25 + off], w3[oc * 800 + (2 * p + 1) * 25 + off]);
    *reinterpret_cast<uint2*>(g_w3i + oc * 1600 + off * 64 + p * 4) = v;
}

// ---------------- conv1 (1->16) FFMA + relu + pool ----------------
__global__ void __launch_bounds__(224) k_conv1(const float* __restrict__ x,
                                               const float* __restrict__ w1,
                                               const float* __restrict__ b1) {
    __shared__ float s_in[32 * 33];
    __shared__ float s_w[400];
    __shared__ float s_b[16];
    const int img = blockIdx.x;
    const int tid = threadIdx.x;

    for (int i = tid; i < 32 * 33; i += 224) s_in[i] = 0.f;
    for (int i = tid; i < 400; i += 224) s_w[i] = w1[i];
    if (tid < 16) s_b[tid] = b1[tid];
    __syncthreads();
    const float* xin = x + img * 784;
    for (int i = tid; i < 784; i += 224) {
        int r = i / 28, c = i - r * 28;
        s_in[(r + 2) * 33 + (c + 2)] = xin[i];
    }
    __syncthreads();

    if (tid < 196) {
        int py = tid / 14, px = tid - py * 14;
        int y0 = 2 * py, x0 = 2 * px;
        float acc[16][4];
#pragma unroll
        for (int j = 0; j < 16; j++) {
            float bv = s_b[j];
            acc[j][0] = bv; acc[j][1] = bv; acc[j][2] = bv; acc[j][3] = bv;
        }
#pragma unroll
        for (int ky = 0; ky < 5; ky++) {
            const float* r0 = &s_in[(y0 + ky) * 33 + x0];
            const float* r1 = r0 + 33;
#pragma unroll
            for (int kx = 0; kx < 5; kx++) {
                float i0 = r0[kx], i1 = r0[kx + 1], i2 = r1[kx], i3 = r1[kx + 1];
#pragma unroll
                for (int j = 0; j < 16; j++) {
                    float wv = s_w[j * 25 + ky * 5 + kx];
                    acc[j][0] += wv * i0; acc[j][1] += wv * i1;
                    acc[j][2] += wv * i2; acc[j][3] += wv * i3;
                }
            }
        }
        float m[16];
#pragma unroll
        for (int j = 0; j < 16; j++)
            m[j] = fmaxf(fmaxf(fmaxf(acc[j][0], acc[j][1]), fmaxf(acc[j][2], acc[j][3])), 0.f);
        __nv_bfloat16* dst = g_a1 + (img * 196 + tid) * 32;
#pragma unroll
        for (int p = 0; p < 8; p++)
            *reinterpret_cast<uint2*>(dst + p * 4) = pack4(m[2 * p], m[2 * p + 1]);
    }
}

// ---------------- conv2 (16->32): 256thr, 8 warps x 4 m-tiles, interleaved LDS.64 ----------------
// smem input: per img 342 px, pixel stride 48 elem (96B, conflict-free); 2 img
// smem weights: 32 oc x 816 elem (1632B stride, conflict-free)
// bytes: in 65664 | w 52224 | pool 12544 | bias 128 = 130560
#define C2_SMEM 130560
__global__ void __launch_bounds__(256) k_conv2(const float* __restrict__ b2) {
    extern __shared__ char smem[];
    __nv_bfloat16* s_in = (__nv_bfloat16*)(smem);               // 2*16416 elem
    __nv_bfloat16* s_w  = (__nv_bfloat16*)(smem + 65664);       // 32*816 elem
    int*           s_pool = (int*)(smem + 117888);              // 2*49*32
    float*         s_bias = (float*)(smem + 130432);

    const int img0 = blockIdx.x * 2;
    const int tid = threadIdx.x;
    const int warp = tid >> 5;
    const int lane = tid & 31;
    const int gid = lane >> 2;
    const int tg  = lane & 3;
    const int kq  = tg * 4;   // elem offset of this thread's k-pair group

    // zero input smem (incl. padding ring)
    uint4 z4 = {0, 0, 0, 0};
    for (int i = tid; i < 4104; i += 256) ((uint4*)s_in)[i] = z4;
    for (int i = tid; i < 3136; i += 256) s_pool[i] = 0;
    if (tid < 32) s_bias[tid] = b2[tid];
    // weights: coalesced copy with pad 800->816
    for (int i = tid; i < 3200; i += 256) {
        int oc = i / 100, r = i - oc * 100;           // 100 uint4 per oc
        *reinterpret_cast<uint4*>(s_w + oc * 816 + r * 8) =
            *reinterpret_cast<const uint4*>(g_w2i + oc * 800 + r * 8);
    }
    __syncthreads();
    // input: per pixel 32 elem = 4 uint4
    for (int i = tid; i < 1568; i += 256) {
        int img = i >> 9 >= 1 ? 1 : 0;  // i/784
        img = i / 784;
        int r = i - img * 784;
        int px = r >> 2, q = r & 3;
        int y = px / 14, xx = px - y * 14;
        *reinterpret_cast<uint4*>(s_in + img * 16416 + ((y + 2) * 19 + (xx + 2)) * 48 + q * 8) =
            *reinterpret_cast<const uint4*>(g_a1 + ((img0 + img) * 196 + px) * 32 + q * 8);
    }
    __syncthreads();

    // 26 m-tiles (2 img x 13), warp owns t = warp + 8*ti
    int aoff0[4], aoff1[4];
#pragma unroll
    for (int ti = 0; ti < 4; ti++) {
        int t = warp + 8 * ti;
        if (t < 26) {
            int img = t / 13, base = (t - img * 13) * 16;
            int p0 = base + gid; if (p0 > 195) p0 = 195;
            int p1 = base + gid + 8; if (p1 > 195) p1 = 195;
            int y0 = p0 / 14, x0 = p0 - y0 * 14;
            int y1 = p1 / 14, x1 = p1 - y1 * 14;
            aoff0[ti] = img * 16416 + (y0 * 19 + x0) * 48 + kq;
            aoff1[ti] = img * 16416 + (y1 * 19 + x1) * 48 + kq;
        }
    }

    float acc[4][4][4];
#pragma unroll
    for (int ti = 0; ti < 4; ti++)
#pragma unroll
        for (int nt = 0; nt < 4; nt++)
#pragma unroll
            for (int j = 0; j < 4; j++) acc[ti][nt][j] = 0.f;

#pragma unroll
    for (int off = 0; off < 25; off++) {
        const int dy = off / 5, dx = off - dy * 5;
        const int dpix = (dy * 19 + dx) * 48;
        uint32_t bh0[4], bh1[4], bl0[4], bl1[4];
#pragma unroll
        for (int nt = 0; nt < 4; nt++) {
            int wr = (nt * 8 + gid) * 816 + off * 32 + kq;
            uint2 w0 = lds_u64(s_w, wr);
            uint2 w1 = lds_u64(s_w, wr + 16);
            bh0[nt] = w0.x; bl0[nt] = w0.y;
            bh1[nt] = w1.x; bl1[nt] = w1.y;
        }
#pragma unroll
        for (int ti = 0; ti < 4; ti++) {
            int t = warp + 8 * ti;
            if (t < 26) {
                int o0 = aoff0[ti] + dpix;
                int o1 = aoff1[ti] + dpix;
                uint2 a00 = lds_u64(s_in, o0);
                uint2 a01 = lds_u64(s_in, o1);
                uint2 a02 = lds_u64(s_in, o0 + 16);
                uint2 a03 = lds_u64(s_in, o1 + 16);
#pragma unroll
                for (int nt = 0; nt < 4; nt++)
                    mma_bf16(acc[ti][nt], a00.x, a01.x, a02.x, a03.x, bh0[nt], bh1[nt]);
#pragma unroll
                for (int nt = 0; nt < 4; nt++)
                    mma_bf16(acc[ti][nt], a00.x, a01.x, a02.x, a03.x, bl0[nt], bl1[nt]);
#pragma unroll
                for (int nt = 0; nt < 4; nt++)
                    mma_bf16(acc[ti][nt], a00.y, a01.y, a02.y, a03.y, bh0[nt], bh1[nt]);
            }
        }
    }

    // epilogue: bias+relu, pool via shared atomicMax on float bits
#pragma unroll
    for (int ti = 0; ti < 4; ti++) {
        int t = warp + 8 * ti;
        if (t < 26) {
            int img = t / 13, base = (t - img * 13) * 16;
            int p0 = base + gid, p1 = p0 + 8;
#pragma unroll
            for (int nt = 0; nt < 4; nt++) {
                int col = nt * 8 + tg * 2;
                float bb0 = s_bias[col], bb1 = s_bias[col + 1];
                if (p0 < 196) {
                    int y = p0 / 14, xx = p0 - y * 14;
                    int pi = img * 1568 + ((y >> 1) * 7 + (xx >> 1)) * 32;
                    atomicMax(&s_pool[pi + col], __float_as_int(fmaxf(acc[ti][nt][0] + bb0, 0.f)));
                    atomicMax(&s_pool[pi + col + 1], __float_as_int(fmaxf(acc[ti][nt][1] + bb1, 0.f)));
                }
                if (p1 < 196) {
                    int y = p1 / 14, xx = p1 - y * 14;
                    int pi = img * 1568 + ((y >> 1) * 7 + (xx >> 1)) * 32;
                    atomicMax(&s_pool[pi + col], __float_as_int(fmaxf(acc[ti][nt][2] + bb0, 0.f)));
                    atomicMax(&s_pool[pi + col + 1], __float_as_int(fmaxf(acc[ti][nt][3] + bb1, 0.f)));
                }
            }
        }
    }
    __syncthreads();
    // write interleaved: [b][px][64 elem]
    for (int i = tid; i < 1568; i += 256) {
        int img = i / 784, r = i - img * 784;
        int px = r >> 4, p = r & 15;
        float v0 = __int_as_float(s_pool[img * 1568 + px * 32 + 2 * p]);
        float v1 = __int_as_float(s_pool[img * 1568 + px * 32 + 2 * p + 1]);
        *reinterpret_cast<uint2*>(g_a2 + ((img0 + img) * 49 + px) * 64 + p * 4) = pack4(v0, v1);
    }
}

// ---------------- conv3 (32->64): 256thr, 8 warps x 2 m-tiles, interleaved LDS.64 ----------------
// smem input: per img 11x12 px grid, pixel stride 80 elem (160B, conflict-free); 4 img
// smem weights: 32 oc x 1616 elem (3232B stride, conflict-free)
// bytes: in 84480 | w 103424 | pool 8192 | bias 128 = 196224
#define C3_SMEM 196224
__global__ void __launch_bounds__(256) k_conv3(const float* __restrict__ b3) {
    extern __shared__ char smem[];
    __nv_bfloat16* s_in = (__nv_bfloat16*)(smem);               // 4*10560 elem
    __nv_bfloat16* s_w  = (__nv_bfloat16*)(smem + 84480);       // 32*1616 elem
    int*           s_pool = (int*)(smem + 187904);              // 4*16*32
    float*         s_bias = (float*)(smem + 196096);

    const int img0 = blockIdx.x * 4;
    const int g = blockIdx.y;        // oc-group 0/1 (32 oc each)
    const int tid = threadIdx.x;
    const int warp = tid >> 5;
    const int lane = tid & 31;
    const int gid = lane >> 2;
    const int tg  = lane & 3;
    const int kq  = tg * 4;

    uint4 z4 = {0, 0, 0, 0};
    for (int i = tid; i < 5280; i += 256) ((uint4*)s_in)[i] = z4;
    for (int i = tid; i < 2048; i += 256) s_pool[i] = 0;
    if (tid < 32) s_bias[tid] = b3[g * 32 + tid];
    // weights: coalesced copy with pad 1600->1616
    const __nv_bfloat16* wg = g_w3i + g * 32 * 1600;
    for (int i = tid; i < 6400; i += 256) {
        int ocl = i / 200, r = i - ocl * 200;        // 200 uint4 per oc
        *reinterpret_cast<uint4*>(s_w + ocl * 1616 + r * 8) =
            *reinterpret_cast<const uint4*>(wg + ocl * 1600 + r * 8);
    }
    __syncthreads();
    for (int i = tid; i < 1568; i += 256) {
        int img = i / 392, r = i - img * 392;
        int px = r >> 3, q = r & 7;
        int y = px / 7, xx = px - y * 7;
        *reinterpret_cast<uint4*>(s_in + img * 10560 + ((y + 2) * 12 + (xx + 2)) * 80 + q * 8) =
            *reinterpret_cast<const uint4*>(g_a2 + ((img0 + img) * 49 + px) * 64 + q * 8);
    }
    __syncthreads();

    // 16 m-tiles (4 img x 4), warp owns t = warp, warp+8
    int aoff0[2], aoff1[2];
#pragma unroll
    for (int ti = 0; ti < 2; ti++) {
        int t = warp + 8 * ti;
        int img = t >> 2, base = (t & 3) * 16;
        int p0 = base + gid; if (p0 > 48) p0 = 48;
        int p1 = base + gid + 8; if (p1 > 48) p1 = 48;
        int y0 = p0 / 7, x0 = p0 - y0 * 7;
        int y1 = p1 / 7, x1 = p1 - y1 * 7;
        aoff0[ti] = img * 10560 + (y0 * 12 + x0) * 80 + kq;
        aoff1[ti] = img * 10560 + (y1 * 12 + x1) * 80 + kq;
    }

    float acc[2][4][4];
#pragma unroll
    for (int ti = 0; ti < 2; ti++)
#pragma unroll
        for (int nt = 0; nt < 4; nt++)
#pragma unroll
            for (int j = 0; j < 4; j++) acc[ti][nt][j] = 0.f;

#pragma unroll
    for (int s = 0; s < 50; s++) {
        const int off = s >> 1;
        const int iche = (s & 1) * 32;       // elem offset of ic-half
        const int dy = off / 5, dx = off - dy * 5;
        const int dbase = (dy * 12 + dx) * 80 + iche;
        uint32_t bh0[4], bh1[4], bl0[4], bl1[4];
#pragma unroll
        for (int nt = 0; nt < 4; nt++) {
            int wr = (nt * 8 + gid) * 1616 + off * 64 + iche + kq;
            uint2 w0 = lds_u64(s_w, wr);
            uint2 w1 = lds_u64(s_w, wr + 16);
            bh0[nt] = w0.x; bl0[nt] = w0.y;
            bh1[nt] = w1.x; bl1[nt] = w1.y;
        }
#pragma unroll
        for (int ti = 0; ti < 2; ti++) {
            int o0 = aoff0[ti] + dbase;
            int o1 = aoff1[ti] + dbase;
            uint2 a00 = lds_u64(s_in, o0);
            uint2 a01 = lds_u64(s_in, o1);
            uint2 a02 = lds_u64(s_in, o0 + 16);
            uint2 a03 = lds_u64(s_in, o1 + 16);
#pragma unroll
            for (int nt = 0; nt < 4; nt++)
                mma_bf16(acc[ti][nt], a00.x, a01.x, a02.x, a03.x, bh0[nt], bh1[nt]);
#pragma unroll
            for (int nt = 0; nt < 4; nt++)
                mma_bf16(acc[ti][nt], a00.x, a01.x, a02.x, a03.x, bl0[nt], bl1[nt]);
#pragma unroll
            for (int nt = 0; nt < 4; nt++)
                mma_bf16(acc[ti][nt], a00.y, a01.y, a02.y, a03.y, bh0[nt], bh1[nt]);
        }
    }

    // epilogue: bias+relu, pool (pad=1): pooled idx = ((y+1)/2)*4 + (x+1)/2
#pragma unroll
    for (int ti = 0; ti < 2; ti++) {
        int t = warp + 8 * ti;
        int img = t >> 2, base = (t & 3) * 16;
        int q0 = base + gid, q1 = q0 + 8;
#pragma unroll
        for (int nt = 0; nt < 4; nt++) {
            int col = nt * 8 + tg * 2;
            float bb0 = s_bias[col], bb1 = s_bias[col + 1];
            if (q0 < 49) {
                int y = q0 / 7, xx = q0 - y * 7;
                int pi = img * 512 + (((y + 1) >> 1) * 4 + ((xx + 1) >> 1)) * 32;
                atomicMax(&s_pool[pi + col], __float_as_int(fmaxf(acc[ti][nt][0] + bb0, 0.f)));
                atomicMax(&s_pool[pi + col + 1], __float_as_int(fmaxf(acc[ti][nt][1] + bb1, 0.f)));
            }
            if (q1 < 49) {
                int y = q1 / 7, xx = q1 - y * 7;
                int pi = img * 512 + (((y + 1) >> 1) * 4 + ((xx + 1) >> 1)) * 32;
                atomicMax(&s_pool[pi + col], __float_as_int(fmaxf(acc[ti][nt][2] + bb0, 0.f)));
                atomicMax(&s_pool[pi + col + 1], __float_as_int(fmaxf(acc[ti][nt][3] + bb1, 0.f)));
            }
        }
    }
    __syncthreads();
    // k = (g*32+ocl)*16 + pidx; pairs over pidx -> interleaved g_a3
    for (int i = tid; i < 1024; i += 256) {
        int img = i >> 8, r = i & 255;
        int ocl = r >> 3, pp = r & 7;
        float v0 = __int_as_float(s_pool[img * 512 + (2 * pp) * 32 + ocl]);
        float v1 = __int_as_float(s_pool[img * 512 + (2 * pp + 1) * 32 + ocl]);
        int gp = ((g * 32 + ocl) * 16 + 2 * pp) >> 1;    // group index = ocg*8 + pp
        *reinterpret_cast<uint2*>(g_a3 + (img0 + img) * 2048 + gp * 4) = pack4(v0, v1);
    }
}

// ---------------- fc1 via bf16x3 MMA, interleaved LDS.64 ----------------
// Block 128x128, 8 warps (4x2), warp m32n64. K staged 64/iter (128 elem interleaved).
#define FC1_STRIDE 144
#define FC1_SMEM (2 * 128 * FC1_STRIDE * 2)   // 73728 B
__global__ void __launch_bounds__(256) k_fc1(const float* __restrict__ bias) {
    extern __shared__ char smem[];
    __nv_bfloat16* s_a = (__nv_bfloat16*)smem;
    __nv_bfloat16* s_b = s_a + 128 * FC1_STRIDE;
    const int tid = threadIdx.x;
    const int warp = tid >> 5, lane = tid & 31;
    const int wm = warp >> 1, wn = warp & 1;
    const int m0 = blockIdx.y * 128, n0 = blockIdx.x * 128;
    const int gid = lane >> 2, tg = lane & 3;
    const int kq = tg * 4;

    float acc[2][8][4];
#pragma unroll
    for (int mt = 0; mt < 2; mt++)
#pragma unroll
        for (int nt = 0; nt < 8; nt++)
#pragma unroll
            for (int j = 0; j < 4; j++) acc[mt][nt][j] = 0.f;

#pragma unroll 1
    for (int k0e = 0; k0e < 2048; k0e += 128) {
        __syncthreads();
        for (int i = tid; i < 4096; i += 256) {
            int j = i & 2047;
            int row = j >> 4, q = j & 15;
            int dst = row * FC1_STRIDE + q * 8;
            if (i < 2048)
                *reinterpret_cast<uint4*>(s_a + dst) =
                    *reinterpret_cast<const uint4*>(g_a3 + (m0 + row) * 2048 + k0e + q * 8);
            else
                *reinterpret_cast<uint4*>(s_b + dst) =
                    *reinterpret_cast<const uint4*>(g_fw1 + (n0 + row) * 2048 + k0e + q * 8);
        }
        __syncthreads();
#pragma unroll
        for (int ks = 0; ks < 4; ks++) {
            int kb = ks * 32 + kq;
            uint32_t ah[2][4], al[2][4];
#pragma unroll
            for (int mt = 0; mt < 2; mt++) {
                int base = (wm * 32 + mt * 16 + gid) * FC1_STRIDE + kb;
                uint2 r0 = lds_u64(s_a, base);
                uint2 r1 = lds_u64(s_a, base + 8 * FC1_STRIDE);
                uint2 r2 = lds_u64(s_a, base + 16);
                uint2 r3 = lds_u64(s_a, base + 8 * FC1_STRIDE + 16);
                ah[mt][0] = r0.x; al[mt][0] = r0.y;
                ah[mt][1] = r1.x; al[mt][1] = r1.y;
                ah[mt][2] = r2.x; al[mt][2] = r2.y;
                ah[mt][3] = r3.x; al[mt][3] = r3.y;
            }
            uint32_t bh[8][2], bl[8][2];
#pragma unroll
            for (int nt = 0; nt < 8; nt++) {
                int base = (wn * 64 + nt * 8 + gid) * FC1_STRIDE + kb;
                uint2 w0 = lds_u64(s_b, base);
                uint2 w1 = lds_u64(s_b, base + 16);
                bh[nt][0] = w0.x; bl[nt][0] = w0.y;
                bh[nt][1] = w1.x; bl[nt][1] = w1.y;
            }
#pragma unroll
            for (int mt = 0; mt < 2; mt++) {
#pragma unroll
                for (int nt = 0; nt < 8; nt++)
                    mma_bf16(acc[mt][nt], ah[mt][0], ah[mt][1], ah[mt][2], ah[mt][3], bh[nt][0], bh[nt][1]);
#pragma unroll
                for (int nt = 0; nt < 8; nt++)
                    mma_bf16(acc[mt][nt], ah[mt][0], ah[mt][1], ah[mt][2], ah[mt][3], bl[nt][0], bl[nt][1]);
#pragma unroll
                for (int nt = 0; nt < 8; nt++)
                    mma_bf16(acc[mt][nt], al[mt][0], al[mt][1], al[mt][2], al[mt][3], bh[nt][0], bh[nt][1]);
            }
        }
    }
#pragma unroll
    for (int mt = 0; mt < 2; mt++) {
        int r = m0 + wm * 32 + mt * 16 + gid;
#pragma unroll
        for (int nt = 0; nt < 8; nt++) {
            int c = n0 + wn * 64 + nt * 8 + tg * 2;
            float b0 = bias[c], b1 = bias[c + 1];
            g_a4[r * 256 + c]           = fmaxf(acc[mt][nt][0] + b0, 0.f);
            g_a4[r * 256 + c + 1]       = fmaxf(acc[mt][nt][1] + b1, 0.f);
            g_a4[(r + 8) * 256 + c]     = fmaxf(acc[mt][nt][2] + b0, 0.f);
            g_a4[(r + 8) * 256 + c + 1] = fmaxf(acc[mt][nt][3] + b1, 0.f);
        }
    }
}

// ---------------- fc2 + log_softmax ----------------
__global__ void __launch_bounds__(256) k_fc2(const float* __restrict__ W,
                                             const float* __restrict__ bias,
                                             float* __restrict__ out) {
    __shared__ float s_w[2560];
    __shared__ float s_b[10];
    const int tid = threadIdx.x;
    for (int i = tid; i < 2560; i += 256) s_w[i] = W[i];
    if (tid < 10) s_b[tid] = bias[tid];
    __syncthreads();

    const int warp = tid >> 5, lane = tid & 31;
    const int row = blockIdx.x * 8 + warp;
    float hv[8];
    const float* hp = g_a4 + row * 256 + lane;
#pragma unroll
    for (int j = 0; j < 8; j++) hv[j] = hp[j * 32];

    float acc[10];
#pragma unroll
    for (int o = 0; o < 10; o++) acc[o] = 0.f;
#pragma unroll
    for (int j = 0; j < 8; j++) {
#pragma unroll
        for (int o = 0; o < 10; o++)
            acc[o] += hv[j] * s_w[o * 256 + lane + j * 32];
    }
#pragma unroll
    for (int o = 0; o < 10; o++) {
#pragma unroll
        for (int off = 16; off > 0; off >>= 1)
            acc[o] += __shfl_xor_sync(0xffffffffu, acc[o], off);
    }
    if (lane == 0) {
        float l[10], m = -1e30f;
#pragma unroll
        for (int o = 0; o < 10; o++) { l[o] = acc[o] + s_b[o]; m = fmaxf(m, l[o]); }
        float s = 0.f;
#pragma unroll
        for (int o = 0; o < 10; o++) s += expf(l[o] - m);
        float ls = logf(s);
        float* op = out + row * 10;
#pragma unroll
        for (int o = 0; o < 10; o++) op[o] = l[o] - m - ls;
    }
}

extern "C" void kernel_launch(void* const* d_in, const int* in_sizes, int n_in,
                              void* d_out, int out_size) {
    const float* x   = (const float*)d_in[0];
    const float* w1  = (const float*)d_in[1];
    const float* b1  = (const float*)d_in[2];
    const float* w2  = (const float*)d_in[3];
    const float* b2  = (const float*)d_in[4];
    const float* w3  = (const float*)d_in[5];
    const float* b3  = (const float*)d_in[6];
    const float* fw1 = (const float*)d_in[7];
    const float* fb1 = (const float*)d_in[8];
    const float* fw2 = (const float*)d_in[9];
    const float* fb2 = (const float*)d_in[10];
    float* out = (float*)d_out;

    cudaFuncSetAttribute(k_conv2, cudaFuncAttributeMaxDynamicSharedMemorySize, C2_SMEM);
    cudaFuncSetAttribute(k_conv3, cudaFuncAttributeMaxDynamicSharedMemorySize, C3_SMEM);
    cudaFuncSetAttribute(k_fc1,   cudaFuncAttributeMaxDynamicSharedMemorySize, FC1_SMEM);

    k_prep_fc1<<<512, 256>>>(fw1);
    k_prep_w2<<<25, 256>>>(w2);
    k_prep_w3<<<100, 256>>>(w3);
    k_conv1<<<BATCH, 224>>>(x, w1, b1);
    k_conv2<<<BATCH / 2, 256, C2_SMEM>>>(b2);
    k_conv3<<<dim3(BATCH / 4, 2), 256, C3_SMEM>>>(b3);
    k_fc1<<<dim3(2, BATCH / 128), 256, FC1_SMEM>>>(fb1);
    k_fc2<<<BATCH / 8, 256>>>(fw2, fb2, out);
}

// round 6
// speedup vs baseline: 1.2006x; 1.0387x over previous
#include <cuda_runtime.h>
#include <cuda_bf16.h>
#include <math.h>
#include <stdint.h>

#define BATCH 8192

// Activations / weights in gmem, bf16 hi/lo interleaved in groups of 4:
//   group p (4 elems): [hi(2p), hi(2p+1), lo(2p), lo(2p+1)]
__device__ __nv_bfloat16 g_a1[BATCH * 196 * 32];   // conv1 out: [b][px][16ic -> 32 elem]
__device__ __nv_bfloat16 g_a2[BATCH * 49 * 64];    // conv2 out: [b][px][32ic -> 64 elem]
__device__ __nv_bfloat16 g_a3[BATCH * 2048];       // conv3 out: [b][1024k -> 2048 elem]
__device__ float g_a4[BATCH * 256];                // fc1 out
__device__ __nv_bfloat16 g_fw1[256 * 2048];        // fc1 W interleaved
__device__ __nv_bfloat16 g_w2i[32 * 800];          // conv2 W: [oc][off*32 + p*4]
__device__ __nv_bfloat16 g_w3i[64 * 1600];         // conv3 W: [oc][off*64 + p*4]

__device__ __forceinline__ uint16_t bfbits(__nv_bfloat16 x) {
    return *reinterpret_cast<uint16_t*>(&x);
}
__device__ __forceinline__ void bf16split(float v, __nv_bfloat16& h, __nv_bfloat16& l) {
    h = __float2bfloat16(v);
    l = __float2bfloat16(v - __bfloat162float(h));
}
__device__ __forceinline__ uint2 pack4(float v0, float v1) {
    __nv_bfloat16 h0, l0, h1, l1;
    bf16split(v0, h0, l0);
    bf16split(v1, h1, l1);
    uint2 r;
    r.x = (uint32_t)bfbits(h0) | ((uint32_t)bfbits(h1) << 16);
    r.y = (uint32_t)bfbits(l0) | ((uint32_t)bfbits(l1) << 16);
    return r;
}

__device__ __forceinline__ void mma_bf16(float* c,
                                         uint32_t a0, uint32_t a1, uint32_t a2, uint32_t a3,
                                         uint32_t b0, uint32_t b1) {
    asm volatile(
        "mma.sync.aligned.m16n8k16.row.col.f32.bf16.bf16.f32 "
        "{%0,%1,%2,%3}, {%4,%5,%6,%7}, {%8,%9}, {%0,%1,%2,%3};"
        : "+f"(c[0]), "+f"(c[1]), "+f"(c[2]), "+f"(c[3])
        : "r"(a0), "r"(a1), "r"(a2), "r"(a3), "r"(b0), "r"(b1));
}

__device__ __forceinline__ uint2 lds_u64(const __nv_bfloat16* p, int elem_idx) {
    return *reinterpret_cast<const uint2*>(p + elem_idx);
}

// ---------------- prep kernels ----------------
__global__ void __launch_bounds__(256) k_prep_fc1(const float* __restrict__ fw1) {
    int i = blockIdx.x * 256 + threadIdx.x;
    int row = i >> 9, p = i & 511;
    uint2 v = pack4(fw1[row * 1024 + 2 * p], fw1[row * 1024 + 2 * p + 1]);
    *reinterpret_cast<uint2*>(g_fw1 + row * 2048 + p * 4) = v;
}
__global__ void __launch_bounds__(256) k_prep_w2(const float* __restrict__ w2) {
    int i = blockIdx.x * 256 + threadIdx.x;
    if (i >= 6400) return;
    int oc = i / 200, r = i - oc * 200;
    int off = r >> 3, p = r & 7;
    uint2 v = pack4(w2[oc * 400 + (2 * p) * 25 + off], w2[oc * 400 + (2 * p + 1) * 25 + off]);
    *reinterpret_cast<uint2*>(g_w2i + oc * 800 + off * 32 + p * 4) = v;
}
__global__ void __launch_bounds__(256) k_prep_w3(const float* __restrict__ w3) {
    int i = blockIdx.x * 256 + threadIdx.x;
    int oc = i / 400, r = i - oc * 400;
    int off = r >> 4, p = r & 15;
    uint2 v = pack4(w3[oc * 800 + (2 * p) * 25 + off], w3[oc * 800 + (2 * p + 1) * 25 + off]);
    *reinterpret_cast<uint2*>(g_w3i + oc * 1600 + off * 64 + p * 4) = v;
}

// ---------------- conv1 (1->16) FFMA + relu + pool: 784 thr, 4oc/thread ----------------
__global__ void __launch_bounds__(784) k_conv1(const float* __restrict__ x,
                                               const float* __restrict__ w1,
                                               const float* __restrict__ b1) {
    __shared__ float s_in[32 * 33];
    __shared__ float s_w[400];
    __shared__ float s_b[16];
    const int img = blockIdx.x;
    const int tid = threadIdx.x;

    if (tid < 400) s_w[tid] = w1[tid];
    if (tid < 16) s_b[tid] = b1[tid];
    for (int i = tid; i < 32 * 33; i += 784) s_in[i] = 0.f;
    __syncthreads();
    if (tid < 784) {
        int r = tid / 28, c = tid - r * 28;
        s_in[(r + 2) * 33 + (c + 2)] = x[img * 784 + tid];
    }
    __syncthreads();

    const int ocq = tid / 196;            // 0..3 -> oc group of 4
    const int sp  = tid - ocq * 196;      // pooled pixel
    const int py = sp / 14, px = sp - py * 14;
    const int y0 = 2 * py, x0 = 2 * px;

    float acc[4][4];
#pragma unroll
    for (int j = 0; j < 4; j++) {
        float bv = s_b[ocq * 4 + j];
        acc[j][0] = bv; acc[j][1] = bv; acc[j][2] = bv; acc[j][3] = bv;
    }
    const float* wb = s_w + ocq * 4 * 25;
#pragma unroll
    for (int ky = 0; ky < 5; ky++) {
        const float* r0 = &s_in[(y0 + ky) * 33 + x0];
        const float* r1 = r0 + 33;
#pragma unroll
        for (int kx = 0; kx < 5; kx++) {
            float i0 = r0[kx], i1 = r0[kx + 1], i2 = r1[kx], i3 = r1[kx + 1];
#pragma unroll
            for (int j = 0; j < 4; j++) {
                float wv = wb[j * 25 + ky * 5 + kx];
                acc[j][0] += wv * i0; acc[j][1] += wv * i1;
                acc[j][2] += wv * i2; acc[j][3] += wv * i3;
            }
        }
    }
    float m[4];
#pragma unroll
    for (int j = 0; j < 4; j++)
        m[j] = fmaxf(fmaxf(fmaxf(acc[j][0], acc[j][1]), fmaxf(acc[j][2], acc[j][3])), 0.f);
    __nv_bfloat16* dst = g_a1 + (img * 196 + sp) * 32;
    *reinterpret_cast<uint2*>(dst + (ocq * 2 + 0) * 4) = pack4(m[0], m[1]);
    *reinterpret_cast<uint2*>(dst + (ocq * 2 + 1) * 4) = pack4(m[2], m[3]);
}

// ---------------- conv2 (16->32): 256thr, 8 warps x 4 m-tiles, interleaved LDS.64 ----------------
#define C2_SMEM 130560
__global__ void __launch_bounds__(256) k_conv2(const float* __restrict__ b2) {
    extern __shared__ char smem[];
    __nv_bfloat16* s_in = (__nv_bfloat16*)(smem);               // 2*16416 elem
    __nv_bfloat16* s_w  = (__nv_bfloat16*)(smem + 65664);       // 32*816 elem
    int*           s_pool = (int*)(smem + 117888);              // 2*49*32
    float*         s_bias = (float*)(smem + 130432);

    const int img0 = blockIdx.x * 2;
    const int tid = threadIdx.x;
    const int warp = tid >> 5;
    const int lane = tid & 31;
    const int gid = lane >> 2;
    const int tg  = lane & 3;
    const int kq  = tg * 4;

    uint4 z4 = {0, 0, 0, 0};
    for (int i = tid; i < 4104; i += 256) ((uint4*)s_in)[i] = z4;
    for (int i = tid; i < 3136; i += 256) s_pool[i] = 0;
    if (tid < 32) s_bias[tid] = b2[tid];
    for (int i = tid; i < 3200; i += 256) {
        int oc = i / 100, r = i - oc * 100;
        *reinterpret_cast<uint4*>(s_w + oc * 816 + r * 8) =
            *reinterpret_cast<const uint4*>(g_w2i + oc * 800 + r * 8);
    }
    __syncthreads();
    for (int i = tid; i < 1568; i += 256) {
        int img = i / 784;
        int r = i - img * 784;
        int px = r >> 2, q = r & 3;
        int y = px / 14, xx = px - y * 14;
        *reinterpret_cast<uint4*>(s_in + img * 16416 + ((y + 2) * 19 + (xx + 2)) * 48 + q * 8) =
            *reinterpret_cast<const uint4*>(g_a1 + ((img0 + img) * 196 + px) * 32 + q * 8);
    }
    __syncthreads();

    int aoff0[4], aoff1[4];
#pragma unroll
    for (int ti = 0; ti < 4; ti++) {
        int t = warp + 8 * ti;
        if (t < 26) {
            int img = t / 13, base = (t - img * 13) * 16;
            int p0 = base + gid; if (p0 > 195) p0 = 195;
            int p1 = base + gid + 8; if (p1 > 195) p1 = 195;
            int y0 = p0 / 14, x0 = p0 - y0 * 14;
            int y1 = p1 / 14, x1 = p1 - y1 * 14;
            aoff0[ti] = img * 16416 + (y0 * 19 + x0) * 48 + kq;
            aoff1[ti] = img * 16416 + (y1 * 19 + x1) * 48 + kq;
        }
    }

    float acc[4][4][4];
#pragma unroll
    for (int ti = 0; ti < 4; ti++)
#pragma unroll
        for (int nt = 0; nt < 4; nt++)
#pragma unroll
            for (int j = 0; j < 4; j++) acc[ti][nt][j] = 0.f;

#pragma unroll
    for (int off = 0; off < 25; off++) {
        const int dy = off / 5, dx = off - dy * 5;
        const int dpix = (dy * 19 + dx) * 48;
        uint32_t bh0[4], bh1[4], bl0[4], bl1[4];
#pragma unroll
        for (int nt = 0; nt < 4; nt++) {
            int wr = (nt * 8 + gid) * 816 + off * 32 + kq;
            uint2 w0 = lds_u64(s_w, wr);
            uint2 w1 = lds_u64(s_w, wr + 16);
            bh0[nt] = w0.x; bl0[nt] = w0.y;
            bh1[nt] = w1.x; bl1[nt] = w1.y;
        }
#pragma unroll
        for (int ti = 0; ti < 4; ti++) {
            int t = warp + 8 * ti;
            if (t < 26) {
                int o0 = aoff0[ti] + dpix;
                int o1 = aoff1[ti] + dpix;
                uint2 a00 = lds_u64(s_in, o0);
                uint2 a01 = lds_u64(s_in, o1);
                uint2 a02 = lds_u64(s_in, o0 + 16);
                uint2 a03 = lds_u64(s_in, o1 + 16);
#pragma unroll
                for (int nt = 0; nt < 4; nt++)
                    mma_bf16(acc[ti][nt], a00.x, a01.x, a02.x, a03.x, bh0[nt], bh1[nt]);
#pragma unroll
                for (int nt = 0; nt < 4; nt++)
                    mma_bf16(acc[ti][nt], a00.x, a01.x, a02.x, a03.x, bl0[nt], bl1[nt]);
#pragma unroll
                for (int nt = 0; nt < 4; nt++)
                    mma_bf16(acc[ti][nt], a00.y, a01.y, a02.y, a03.y, bh0[nt], bh1[nt]);
            }
        }
    }

#pragma unroll
    for (int ti = 0; ti < 4; ti++) {
        int t = warp + 8 * ti;
        if (t < 26) {
            int img = t / 13, base = (t - img * 13) * 16;
            int p0 = base + gid, p1 = p0 + 8;
#pragma unroll
            for (int nt = 0; nt < 4; nt++) {
                int col = nt * 8 + tg * 2;
                float bb0 = s_bias[col], bb1 = s_bias[col + 1];
                if (p0 < 196) {
                    int y = p0 / 14, xx = p0 - y * 14;
                    int pi = img * 1568 + ((y >> 1) * 7 + (xx >> 1)) * 32;
                    atomicMax(&s_pool[pi + col], __float_as_int(fmaxf(acc[ti][nt][0] + bb0, 0.f)));
                    atomicMax(&s_pool[pi + col + 1], __float_as_int(fmaxf(acc[ti][nt][1] + bb1, 0.f)));
                }
                if (p1 < 196) {
                    int y = p1 / 14, xx = p1 - y * 14;
                    int pi = img * 1568 + ((y >> 1) * 7 + (xx >> 1)) * 32;
                    atomicMax(&s_pool[pi + col], __float_as_int(fmaxf(acc[ti][nt][2] + bb0, 0.f)));
                    atomicMax(&s_pool[pi + col + 1], __float_as_int(fmaxf(acc[ti][nt][3] + bb1, 0.f)));
                }
            }
        }
    }
    __syncthreads();
    for (int i = tid; i < 1568; i += 256) {
        int img = i / 784, r = i - img * 784;
        int px = r >> 4, p = r & 15;
        float v0 = __int_as_float(s_pool[img * 1568 + px * 32 + 2 * p]);
        float v1 = __int_as_float(s_pool[img * 1568 + px * 32 + 2 * p + 1]);
        *reinterpret_cast<uint2*>(g_a2 + ((img0 + img) * 49 + px) * 64 + p * 4) = pack4(v0, v1);
    }
}

// ---------------- conv3 (32->64): block = 2 img x 16 oc, 96KB smem -> 2 CTA/SM ----------------
// smem: in 2*10560 elem (42240B) | w 16*1616 elem (51712B) | pool 2*256 int (2048B) | bias 64B
#define C3_SMEM (42240 + 51712 + 2048 + 64)
__global__ void __launch_bounds__(256) k_conv3(const float* __restrict__ b3) {
    extern __shared__ char smem[];
    __nv_bfloat16* s_in = (__nv_bfloat16*)(smem);               // 2*10560 elem
    __nv_bfloat16* s_w  = (__nv_bfloat16*)(smem + 42240);       // 16*1616 elem
    int*           s_pool = (int*)(smem + 93952);               // 2*16px*16oc
    float*         s_bias = (float*)(smem + 96000);

    const int img0 = blockIdx.x * 2;
    const int g = blockIdx.y;        // oc-group 0..3 (16 oc each)
    const int tid = threadIdx.x;
    const int warp = tid >> 5;
    const int lane = tid & 31;
    const int gid = lane >> 2;
    const int tg  = lane & 3;
    const int kq  = tg * 4;

    uint4 z4 = {0, 0, 0, 0};
    for (int i = tid; i < 2640; i += 256) ((uint4*)s_in)[i] = z4;
    for (int i = tid; i < 512; i += 256) s_pool[i] = 0;
    if (tid < 16) s_bias[tid] = b3[g * 16 + tid];
    const __nv_bfloat16* wg = g_w3i + g * 16 * 1600;
    for (int i = tid; i < 3200; i += 256) {
        int ocl = i / 200, r = i - ocl * 200;
        *reinterpret_cast<uint4*>(s_w + ocl * 1616 + r * 8) =
            *reinterpret_cast<const uint4*>(wg + ocl * 1600 + r * 8);
    }
    __syncthreads();
    for (int i = tid; i < 784; i += 256) {
        int img = i / 392, r = i - img * 392;
        int px = r >> 3, q = r & 7;
        int y = px / 7, xx = px - y * 7;
        *reinterpret_cast<uint4*>(s_in + img * 10560 + ((y + 2) * 12 + (xx + 2)) * 80 + q * 8) =
            *reinterpret_cast<const uint4*>(g_a2 + ((img0 + img) * 49 + px) * 64 + q * 8);
    }
    __syncthreads();

    // 8 m-tiles (2 img x 4), one per warp
    const int timg = warp >> 2, base = (warp & 3) * 16;
    int p0 = base + gid; if (p0 > 48) p0 = 48;
    int p1 = base + gid + 8; if (p1 > 48) p1 = 48;
    int y0 = p0 / 7, x0 = p0 - y0 * 7;
    int y1 = p1 / 7, x1 = p1 - y1 * 7;
    const int aoff0 = timg * 10560 + (y0 * 12 + x0) * 80 + kq;
    const int aoff1 = timg * 10560 + (y1 * 12 + x1) * 80 + kq;

    float acc[2][4];
#pragma unroll
    for (int nt = 0; nt < 2; nt++)
#pragma unroll
        for (int j = 0; j < 4; j++) acc[nt][j] = 0.f;

#pragma unroll
    for (int s = 0; s < 50; s++) {
        const int off = s >> 1;
        const int iche = (s & 1) * 32;
        const int dy = off / 5, dx = off - dy * 5;
        const int dbase = (dy * 12 + dx) * 80 + iche;
        uint32_t bh0[2], bh1[2], bl0[2], bl1[2];
#pragma unroll
        for (int nt = 0; nt < 2; nt++) {
            int wr = (nt * 8 + gid) * 1616 + off * 64 + iche + kq;
            uint2 w0 = lds_u64(s_w, wr);
            uint2 w1 = lds_u64(s_w, wr + 16);
            bh0[nt] = w0.x; bl0[nt] = w0.y;
            bh1[nt] = w1.x; bl1[nt] = w1.y;
        }
        int o0 = aoff0 + dbase;
        int o1 = aoff1 + dbase;
        uint2 a00 = lds_u64(s_in, o0);
        uint2 a01 = lds_u64(s_in, o1);
        uint2 a02 = lds_u64(s_in, o0 + 16);
        uint2 a03 = lds_u64(s_in, o1 + 16);
#pragma unroll
        for (int nt = 0; nt < 2; nt++)
            mma_bf16(acc[nt], a00.x, a01.x, a02.x, a03.x, bh0[nt], bh1[nt]);
#pragma unroll
        for (int nt = 0; nt < 2; nt++)
            mma_bf16(acc[nt], a00.x, a01.x, a02.x, a03.x, bl0[nt], bl1[nt]);
#pragma unroll
        for (int nt = 0; nt < 2; nt++)
            mma_bf16(acc[nt], a00.y, a01.y, a02.y, a03.y, bh0[nt], bh1[nt]);
    }

    // epilogue: bias + relu, pool (pad=1); s_pool stride 16 per pooled px
    {
        int q0 = base + gid, q1 = q0 + 8;
#pragma unroll
        for (int nt = 0; nt < 2; nt++) {
            int col = nt * 8 + tg * 2;
            float bb0 = s_bias[col], bb1 = s_bias[col + 1];
            if (q0 < 49) {
                int y = q0 / 7, xx = q0 - y * 7;
                int pi = timg * 256 + (((y + 1) >> 1) * 4 + ((xx + 1) >> 1)) * 16;
                atomicMax(&s_pool[pi + col], __float_as_int(fmaxf(acc[nt][0] + bb0, 0.f)));
                atomicMax(&s_pool[pi + col + 1], __float_as_int(fmaxf(acc[nt][1] + bb1, 0.f)));
            }
            if (q1 < 49) {
                int y = q1 / 7, xx = q1 - y * 7;
                int pi = timg * 256 + (((y + 1) >> 1) * 4 + ((xx + 1) >> 1)) * 16;
                atomicMax(&s_pool[pi + col], __float_as_int(fmaxf(acc[nt][2] + bb0, 0.f)));
                atomicMax(&s_pool[pi + col + 1], __float_as_int(fmaxf(acc[nt][3] + bb1, 0.f)));
            }
        }
    }
    __syncthreads();
    // k = (g*16+ocl)*16 + pidx; pair over pidx -> interleaved group gp = (g*16+ocl)*8 + pp
    for (int j = tid; j < 256; j += 256) {
        int img = j >> 7, r = j & 127;
        int ocl = r >> 3, pp = r & 7;
        float v0 = __int_as_float(s_pool[img * 256 + (2 * pp) * 16 + ocl]);
        float v1 = __int_as_float(s_pool[img * 256 + (2 * pp + 1) * 16 + ocl]);
        int gp = (g * 16 + ocl) * 8 + pp;
        *reinterpret_cast<uint2*>(g_a3 + (img0 + img) * 2048 + gp * 4) = pack4(v0, v1);
    }
}

// ---------------- fc1 via bf16x3 MMA, interleaved LDS.64 ----------------
#define FC1_STRIDE 144
#define FC1_SMEM (2 * 128 * FC1_STRIDE * 2)
__global__ void __launch_bounds__(256) k_fc1(const float* __restrict__ bias) {
    extern __shared__ char smem[];
    __nv_bfloat16* s_a = (__nv_bfloat16*)smem;
    __nv_bfloat16* s_b = s_a + 128 * FC1_STRIDE;
    const int tid = threadIdx.x;
    const int warp = tid >> 5, lane = tid & 31;
    const int wm = warp >> 1, wn = warp & 1;
    const int m0 = blockIdx.y * 128, n0 = blockIdx.x * 128;
    const int gid = lane >> 2, tg = lane & 3;
    const int kq = tg * 4;

    float acc[2][8][4];
#pragma unroll
    for (int mt = 0; mt < 2; mt++)
#pragma unroll
        for (int nt = 0; nt < 8; nt++)
#pragma unroll
            for (int j = 0; j < 4; j++) acc[mt][nt][j] = 0.f;

#pragma unroll 1
    for (int k0e = 0; k0e < 2048; k0e += 128) {
        __syncthreads();
        for (int i = tid; i < 4096; i += 256) {
            int j = i & 2047;
            int row = j >> 4, q = j & 15;
            int dst = row * FC1_STRIDE + q * 8;
            if (i < 2048)
                *reinterpret_cast<uint4*>(s_a + dst) =
                    *reinterpret_cast<const uint4*>(g_a3 + (m0 + row) * 2048 + k0e + q * 8);
            else
                *reinterpret_cast<uint4*>(s_b + dst) =
                    *reinterpret_cast<const uint4*>(g_fw1 + (n0 + row) * 2048 + k0e + q * 8);
        }
        __syncthreads();
#pragma unroll
        for (int ks = 0; ks < 4; ks++) {
            int kb = ks * 32 + kq;
            uint32_t ah[2][4], al[2][4];
#pragma unroll
            for (int mt = 0; mt < 2; mt++) {
                int base = (wm * 32 + mt * 16 + gid) * FC1_STRIDE + kb;
                uint2 r0 = lds_u64(s_a, base);
                uint2 r1 = lds_u64(s_a, base + 8 * FC1_STRIDE);
                uint2 r2 = lds_u64(s_a, base + 16);
                uint2 r3 = lds_u64(s_a, base + 8 * FC1_STRIDE + 16);
                ah[mt][0] = r0.x; al[mt][0] = r0.y;
                ah[mt][1] = r1.x; al[mt][1] = r1.y;
                ah[mt][2] = r2.x; al[mt][2] = r2.y;
                ah[mt][3] = r3.x; al[mt][3] = r3.y;
            }
            uint32_t bh[8][2], bl[8][2];
#pragma unroll
            for (int nt = 0; nt < 8; nt++) {
                int base = (wn * 64 + nt * 8 + gid) * FC1_STRIDE + kb;
                uint2 w0 = lds_u64(s_b, base);
                uint2 w1 = lds_u64(s_b, base + 16);
                bh[nt][0] = w0.x; bl[nt][0] = w0.y;
                bh[nt][1] = w1.x; bl[nt][1] = w1.y;
            }
#pragma unroll
            for (int mt = 0; mt < 2; mt++) {
#pragma unroll
                for (int nt = 0; nt < 8; nt++)
                    mma_bf16(acc[mt][nt], ah[mt][0], ah[mt][1], ah[mt][2], ah[mt][3], bh[nt][0], bh[nt][1]);
#pragma unroll
                for (int nt = 0; nt < 8; nt++)
                    mma_bf16(acc[mt][nt], ah[mt][0], ah[mt][1], ah[mt][2], ah[mt][3], bl[nt][0], bl[nt][1]);
#pragma unroll
                for (int nt = 0; nt < 8; nt++)
                    mma_bf16(acc[mt][nt], al[mt][0], al[mt][1], al[mt][2], al[mt][3], bh[nt][0], bh[nt][1]);
            }
        }
    }
#pragma unroll
    for (int mt = 0; mt < 2; mt++) {
        int r = m0 + wm * 32 + mt * 16 + gid;
#pragma unroll
        for (int nt = 0; nt < 8; nt++) {
            int c = n0 + wn * 64 + nt * 8 + tg * 2;
            float b0 = bias[c], b1 = bias[c + 1];
            g_a4[r * 256 + c]           = fmaxf(acc[mt][nt][0] + b0, 0.f);
            g_a4[r * 256 + c + 1]       = fmaxf(acc[mt][nt][1] + b1, 0.f);
            g_a4[(r + 8) * 256 + c]     = fmaxf(acc[mt][nt][2] + b0, 0.f);
            g_a4[(r + 8) * 256 + c + 1] = fmaxf(acc[mt][nt][3] + b1, 0.f);
        }
    }
}

// ---------------- fc2 + log_softmax ----------------
__global__ void __launch_bounds__(256) k_fc2(const float* __restrict__ W,
                                             const float* __restrict__ bias,
                                             float* __restrict__ out) {
    __shared__ float s_w[2560];
    __shared__ float s_b[10];
    const int tid = threadIdx.x;
    for (int i = tid; i < 2560; i += 256) s_w[i] = W[i];
    if (tid < 10) s_b[tid] = bias[tid];
    __syncthreads();

    const int warp = tid >> 5, lane = tid & 31;
    const int row = blockIdx.x * 8 + warp;
    float hv[8];
    const float* hp = g_a4 + row * 256 + lane;
#pragma unroll
    for (int j = 0; j < 8; j++) hv[j] = hp[j * 32];

    float acc[10];
#pragma unroll
    for (int o = 0; o < 10; o++) acc[o] = 0.f;
#pragma unroll
    for (int j = 0; j < 8; j++) {
#pragma unroll
        for (int o = 0; o < 10; o++)
            acc[o] += hv[j] * s_w[o * 256 + lane + j * 32];
    }
#pragma unroll
    for (int o = 0; o < 10; o++) {
#pragma unroll
        for (int off = 16; off > 0; off >>= 1)
            acc[o] += __shfl_xor_sync(0xffffffffu, acc[o], off);
    }
    if (lane == 0) {
        float l[10], m = -1e30f;
#pragma unroll
        for (int o = 0; o < 10; o++) { l[o] = acc[o] + s_b[o]; m = fmaxf(m, l[o]); }
        float s = 0.f;
#pragma unroll
        for (int o = 0; o < 10; o++) s += expf(l[o] - m);
        float ls = logf(s);
        float* op = out + row * 10;
#pragma unroll
        for (int o = 0; o < 10; o++) op[o] = l[o] - m - ls;
    }
}

extern "C" void kernel_launch(void* const* d_in, const int* in_sizes, int n_in,
                              void* d_out, int out_size) {
    const float* x   = (const float*)d_in[0];
    const float* w1  = (const float*)d_in[1];
    const float* b1  = (const float*)d_in[2];
    const float* w2  = (const float*)d_in[3];
    const float* b2  = (const float*)d_in[4];
    const float* w3  = (const float*)d_in[5];
    const float* b3  = (const float*)d_in[6];
    const float* fw1 = (const float*)d_in[7];
    const float* fb1 = (const float*)d_in[8];
    const float* fw2 = (const float*)d_in[9];
    const float* fb2 = (const float*)d_in[10];
    float* out = (float*)d_out;

    cudaFuncSetAttribute(k_conv2, cudaFuncAttributeMaxDynamicSharedMemorySize, C2_SMEM);
    cudaFuncSetAttribute(k_conv3, cudaFuncAttributeMaxDynamicSharedMemorySize, C3_SMEM);
    cudaFuncSetAttribute(k_fc1,   cudaFuncAttributeMaxDynamicSharedMemorySize, FC1_SMEM);

    k_prep_fc1<<<512, 256>>>(fw1);
    k_prep_w2<<<25, 256>>>(w2);
    k_prep_w3<<<100, 256>>>(w3);
    k_conv1<<<BATCH, 784>>>(x, w1, b1);
    k_conv2<<<BATCH / 2, 256, C2_SMEM>>>(b2);
    k_conv3<<<dim3(BATCH / 2, 4), 256, C3_SMEM>>>(b3);
    k_fc1<<<dim3(2, BATCH / 128), 256, FC1_SMEM>>>(fb1);
    k_fc2<<<BATCH / 8, 256>>>(fw2, fb2, out);
}

// round 7
// speedup vs baseline: 1.4135x; 1.1774x over previous
#include <cuda_runtime.h>
#include <cuda_bf16.h>
#include <math.h>
#include <stdint.h>

#define BATCH 8192

// Activations / weights in gmem, bf16 hi/lo interleaved in groups of 4:
//   group p (4 elems): [hi(2p), hi(2p+1), lo(2p), lo(2p+1)]
__device__ __nv_bfloat16 g_a1[BATCH * 196 * 32];   // conv1 out: [b][px][16ic -> 32 elem]
__device__ __nv_bfloat16 g_a2[BATCH * 49 * 64];    // conv2 out: [b][px][32ic -> 64 elem]
__device__ __nv_bfloat16 g_a3[BATCH * 2048];       // conv3 out: [b][1024k -> 2048 elem]
__device__ float g_a4[BATCH * 256];                // fc1 out
__device__ __nv_bfloat16 g_fw1[256 * 2048];        // fc1 W interleaved
__device__ __nv_bfloat16 g_w2i[32 * 800];          // conv2 W: [oc][off*32 + p*4]
__device__ __nv_bfloat16 g_w3i[64 * 1600];         // conv3 W: [oc][off*64 + p*4]

__device__ __forceinline__ uint16_t bfbits(__nv_bfloat16 x) {
    return *reinterpret_cast<uint16_t*>(&x);
}
__device__ __forceinline__ void bf16split(float v, __nv_bfloat16& h, __nv_bfloat16& l) {
    h = __float2bfloat16(v);
    l = __float2bfloat16(v - __bfloat162float(h));
}
__device__ __forceinline__ uint2 pack4(float v0, float v1) {
    __nv_bfloat16 h0, l0, h1, l1;
    bf16split(v0, h0, l0);
    bf16split(v1, h1, l1);
    uint2 r;
    r.x = (uint32_t)bfbits(h0) | ((uint32_t)bfbits(h1) << 16);
    r.y = (uint32_t)bfbits(l0) | ((uint32_t)bfbits(l1) << 16);
    return r;
}

__device__ __forceinline__ void mma_bf16(float* c,
                                         uint32_t a0, uint32_t a1, uint32_t a2, uint32_t a3,
                                         uint32_t b0, uint32_t b1) {
    asm volatile(
        "mma.sync.aligned.m16n8k16.row.col.f32.bf16.bf16.f32 "
        "{%0,%1,%2,%3}, {%4,%5,%6,%7}, {%8,%9}, {%0,%1,%2,%3};"
        : "+f"(c[0]), "+f"(c[1]), "+f"(c[2]), "+f"(c[3])
        : "r"(a0), "r"(a1), "r"(a2), "r"(a3), "r"(b0), "r"(b1));
}

__device__ __forceinline__ uint2 lds_u64(const __nv_bfloat16* p, int elem_idx) {
    return *reinterpret_cast<const uint2*>(p + elem_idx);
}

// ---------------- prep kernels ----------------
__global__ void __launch_bounds__(256) k_prep_fc1(const float* __restrict__ fw1) {
    int i = blockIdx.x * 256 + threadIdx.x;
    int row = i >> 9, p = i & 511;
    uint2 v = pack4(fw1[row * 1024 + 2 * p], fw1[row * 1024 + 2 * p + 1]);
    *reinterpret_cast<uint2*>(g_fw1 + row * 2048 + p * 4) = v;
}
__global__ void __launch_bounds__(256) k_prep_w2(const float* __restrict__ w2) {
    int i = blockIdx.x * 256 + threadIdx.x;
    if (i >= 6400) return;
    int oc = i / 200, r = i - oc * 200;
    int off = r >> 3, p = r & 7;
    uint2 v = pack4(w2[oc * 400 + (2 * p) * 25 + off], w2[oc * 400 + (2 * p + 1) * 25 + off]);
    *reinterpret_cast<uint2*>(g_w2i + oc * 800 + off * 32 + p * 4) = v;
}
__global__ void __launch_bounds__(256) k_prep_w3(const float* __restrict__ w3) {
    int i = blockIdx.x * 256 + threadIdx.x;
    int oc = i / 400, r = i - oc * 400;
    int off = r >> 4, p = r & 15;
    uint2 v = pack4(w3[oc * 800 + (2 * p) * 25 + off], w3[oc * 800 + (2 * p + 1) * 25 + off]);
    *reinterpret_cast<uint2*>(g_w3i + oc * 1600 + off * 64 + p * 4) = v;
}

// ---------------- conv1 (1->16) FFMA + relu + pool: register patch ----------------
__global__ void __launch_bounds__(784) k_conv1(const float* __restrict__ x,
                                               const float* __restrict__ w1,
                                               const float* __restrict__ b1) {
    __shared__ float s_in[32 * 33];
    __shared__ float s_w[400];
    __shared__ float s_b[16];
    const int img = blockIdx.x;
    const int tid = threadIdx.x;

    if (tid < 400) s_w[tid] = w1[tid];
    if (tid < 16) s_b[tid] = b1[tid];
    for (int i = tid; i < 32 * 33; i += 784) s_in[i] = 0.f;
    __syncthreads();
    {
        int r = tid / 28, c = tid - r * 28;
        s_in[(r + 2) * 33 + (c + 2)] = x[img * 784 + tid];
    }
    __syncthreads();

    const int ocq = tid / 196;
    const int sp  = tid - ocq * 196;
    const int py = sp / 14, px = sp - py * 14;
    const int y0 = 2 * py, x0 = 2 * px;

    // hoist 6x6 input patch to registers
    float patch[36];
#pragma unroll
    for (int iy = 0; iy < 6; iy++)
#pragma unroll
        for (int ix = 0; ix < 6; ix++)
            patch[iy * 6 + ix] = s_in[(y0 + iy) * 33 + x0 + ix];

    float acc[4][4];
#pragma unroll
    for (int j = 0; j < 4; j++) {
        float bv = s_b[ocq * 4 + j];
        acc[j][0] = bv; acc[j][1] = bv; acc[j][2] = bv; acc[j][3] = bv;
    }
    const float* wb = s_w + ocq * 100;
#pragma unroll
    for (int j = 0; j < 4; j++) {
#pragma unroll
        for (int ky = 0; ky < 5; ky++) {
#pragma unroll
            for (int kx = 0; kx < 5; kx++) {
                float wv = wb[j * 25 + ky * 5 + kx];
                acc[j][0] += wv * patch[ky * 6 + kx];
                acc[j][1] += wv * patch[ky * 6 + kx + 1];
                acc[j][2] += wv * patch[(ky + 1) * 6 + kx];
                acc[j][3] += wv * patch[(ky + 1) * 6 + kx + 1];
            }
        }
    }
    float m[4];
#pragma unroll
    for (int j = 0; j < 4; j++)
        m[j] = fmaxf(fmaxf(fmaxf(acc[j][0], acc[j][1]), fmaxf(acc[j][2], acc[j][3])), 0.f);
    __nv_bfloat16* dst = g_a1 + (img * 196 + sp) * 32;
    *reinterpret_cast<uint2*>(dst + (ocq * 2 + 0) * 4) = pack4(m[0], m[1]);
    *reinterpret_cast<uint2*>(dst + (ocq * 2 + 1) * 4) = pack4(m[2], m[3]);
}

// ---------------- conv2 (16->32): 4 img/block, 512 thr (16 warps), 49 m-tiles ----------------
// smem elems: in 4*15552 (18x18 px grid, 48/px) | w 32*816 | pool 4*1568 int | bias | lut
#define C2_SMEM 201984
__global__ void __launch_bounds__(512) k_conv2(const float* __restrict__ b2) {
    extern __shared__ char smem[];
    __nv_bfloat16* s_in = (__nv_bfloat16*)(smem);               // 62208 elem
    __nv_bfloat16* s_w  = (__nv_bfloat16*)(smem + 124416);      // 26112 elem
    int*           s_pool = (int*)(smem + 176640);              // 6272 int
    float*         s_bias = (float*)(smem + 201728);
    int*           s_lut  = (int*)(smem + 201856);              // 25

    const int img0 = blockIdx.x * 4;
    const int tid = threadIdx.x;
    const int warp = tid >> 5;
    const int lane = tid & 31;
    const int gid = lane >> 2;
    const int tg  = lane & 3;
    const int kq  = tg * 4;

    uint4 z4 = {0, 0, 0, 0};
    for (int i = tid; i < 7776; i += 512) ((uint4*)s_in)[i] = z4;
    for (int i = tid; i < 6272; i += 512) s_pool[i] = 0;
    if (tid < 32) s_bias[tid] = b2[tid];
    if (tid < 25) { int dy = tid / 5, dx = tid - dy * 5; s_lut[tid] = (dy * 18 + dx) * 48; }
    for (int i = tid; i < 3200; i += 512) {
        int oc = i / 100, r = i - oc * 100;
        *reinterpret_cast<uint4*>(s_w + oc * 816 + r * 8) =
            *reinterpret_cast<const uint4*>(g_w2i + oc * 800 + r * 8);
    }
    __syncthreads();
    for (int i = tid; i < 3136; i += 512) {
        int img = i / 784, r = i - img * 784;
        int px = r >> 2, q = r & 3;
        int y = px / 14, xx = px - y * 14;
        *reinterpret_cast<uint4*>(s_in + img * 15552 + ((y + 2) * 18 + (xx + 2)) * 48 + q * 8) =
            *reinterpret_cast<const uint4*>(g_a1 + ((img0 + img) * 196 + px) * 32 + q * 8);
    }
    __syncthreads();

    // 49 m-tiles over 784 rows (img*196+px); warp owns t = warp + 16*ti
    int aoff0[4], aoff1[4];
#pragma unroll
    for (int ti = 0; ti < 4; ti++) {
        int t = warp + 16 * ti;
        if (t < 49) {
            int r0 = t * 16 + gid, r1 = r0 + 8;
            int i0 = r0 / 196, p0 = r0 - i0 * 196;
            int i1 = r1 / 196, p1 = r1 - i1 * 196;
            int y0 = p0 / 14, x0 = p0 - y0 * 14;
            int y1 = p1 / 14, x1 = p1 - y1 * 14;
            aoff0[ti] = i0 * 15552 + (y0 * 18 + x0) * 48 + kq;
            aoff1[ti] = i1 * 15552 + (y1 * 18 + x1) * 48 + kq;
        }
    }

    float acc[4][4][4];
#pragma unroll
    for (int ti = 0; ti < 4; ti++)
#pragma unroll
        for (int nt = 0; nt < 4; nt++)
#pragma unroll
            for (int j = 0; j < 4; j++) acc[ti][nt][j] = 0.f;

    int wrb[4];
#pragma unroll
    for (int nt = 0; nt < 4; nt++) wrb[nt] = (nt * 8 + gid) * 816 + kq;

#pragma unroll 1
    for (int off = 0; off < 25; off++) {
        const int dpix = s_lut[off];
        const int wofs = off * 32;
        uint32_t bh0[4], bh1[4], bl0[4], bl1[4];
#pragma unroll
        for (int nt = 0; nt < 4; nt++) {
            uint2 w0 = lds_u64(s_w, wrb[nt] + wofs);
            uint2 w1 = lds_u64(s_w, wrb[nt] + wofs + 16);
            bh0[nt] = w0.x; bl0[nt] = w0.y;
            bh1[nt] = w1.x; bl1[nt] = w1.y;
        }
#pragma unroll
        for (int ti = 0; ti < 4; ti++) {
            int t = warp + 16 * ti;
            if (t < 49) {
                int o0 = aoff0[ti] + dpix;
                int o1 = aoff1[ti] + dpix;
                uint2 a00 = lds_u64(s_in, o0);
                uint2 a01 = lds_u64(s_in, o1);
                uint2 a02 = lds_u64(s_in, o0 + 16);
                uint2 a03 = lds_u64(s_in, o1 + 16);
#pragma unroll
                for (int nt = 0; nt < 4; nt++)
                    mma_bf16(acc[ti][nt], a00.x, a01.x, a02.x, a03.x, bh0[nt], bh1[nt]);
#pragma unroll
                for (int nt = 0; nt < 4; nt++)
                    mma_bf16(acc[ti][nt], a00.x, a01.x, a02.x, a03.x, bl0[nt], bl1[nt]);
#pragma unroll
                for (int nt = 0; nt < 4; nt++)
                    mma_bf16(acc[ti][nt], a00.y, a01.y, a02.y, a03.y, bh0[nt], bh1[nt]);
            }
        }
    }

    // epilogue: bias + relu, pool via shared atomicMax
#pragma unroll
    for (int ti = 0; ti < 4; ti++) {
        int t = warp + 16 * ti;
        if (t < 49) {
            int r0 = t * 16 + gid, r1 = r0 + 8;
            int i0 = r0 / 196, p0 = r0 - i0 * 196;
            int i1 = r1 / 196, p1 = r1 - i1 * 196;
            int y0 = p0 / 14, x0 = p0 - y0 * 14;
            int y1 = p1 / 14, x1 = p1 - y1 * 14;
            int pi0 = i0 * 1568 + ((y0 >> 1) * 7 + (x0 >> 1)) * 32;
            int pi1 = i1 * 1568 + ((y1 >> 1) * 7 + (x1 >> 1)) * 32;
#pragma unroll
            for (int nt = 0; nt < 4; nt++) {
                int col = nt * 8 + tg * 2;
                float bb0 = s_bias[col], bb1 = s_bias[col + 1];
                atomicMax(&s_pool[pi0 + col], __float_as_int(fmaxf(acc[ti][nt][0] + bb0, 0.f)));
                atomicMax(&s_pool[pi0 + col + 1], __float_as_int(fmaxf(acc[ti][nt][1] + bb1, 0.f)));
                atomicMax(&s_pool[pi1 + col], __float_as_int(fmaxf(acc[ti][nt][2] + bb0, 0.f)));
                atomicMax(&s_pool[pi1 + col + 1], __float_as_int(fmaxf(acc[ti][nt][3] + bb1, 0.f)));
            }
        }
    }
    __syncthreads();
    for (int i = tid; i < 3136; i += 512) {
        int img = i / 784, r = i - img * 784;
        int px = r >> 4, p = r & 15;
        float v0 = __int_as_float(s_pool[img * 1568 + px * 32 + 2 * p]);
        float v1 = __int_as_float(s_pool[img * 1568 + px * 32 + 2 * p + 1]);
        *reinterpret_cast<uint2*>(g_a2 + ((img0 + img) * 49 + px) * 64 + p * 4) = pack4(v0, v1);
    }
}

// ---------------- conv3 (32->64): 5 img/block, 512 thr (16 warps), 16 m-tiles, 32 oc ----------------
// smem elems: in 5*9680 (11x11 px grid, 80/px) | w 32*1616 | pool 5*512 int | bias | lut
#define C3_SMEM 210720
__global__ void __launch_bounds__(512) k_conv3(const float* __restrict__ b3) {
    extern __shared__ char smem[];
    __nv_bfloat16* s_in = (__nv_bfloat16*)(smem);               // 48400 elem
    __nv_bfloat16* s_w  = (__nv_bfloat16*)(smem + 96800);       // 51712 elem
    int*           s_pool = (int*)(smem + 200224);              // 2560 int
    float*         s_bias = (float*)(smem + 210464);
    int*           s_lut  = (int*)(smem + 210592);              // 25

    const int img0 = blockIdx.x * 5;
    const int g = blockIdx.y;        // oc-group 0/1 (32 oc each)
    const int tid = threadIdx.x;
    const int warp = tid >> 5;       // 0..15 = m-tile
    const int lane = tid & 31;
    const int gid = lane >> 2;
    const int tg  = lane & 3;
    const int kq  = tg * 4;

    uint4 z4 = {0, 0, 0, 0};
    for (int i = tid; i < 6050; i += 512) ((uint4*)s_in)[i] = z4;
    for (int i = tid; i < 2560; i += 512) s_pool[i] = 0;
    if (tid < 32) s_bias[tid] = b3[g * 32 + tid];
    if (tid < 25) { int dy = tid / 5, dx = tid - dy * 5; s_lut[tid] = (dy * 11 + dx) * 80; }
    const __nv_bfloat16* wg = g_w3i + g * 32 * 1600;
    for (int i = tid; i < 6400; i += 512) {
        int ocl = i / 200, r = i - ocl * 200;
        *reinterpret_cast<uint4*>(s_w + ocl * 1616 + r * 8) =
            *reinterpret_cast<const uint4*>(wg + ocl * 1600 + r * 8);
    }
    __syncthreads();
    for (int i = tid; i < 1960; i += 512) {
        int img = i / 392, r = i - img * 392;
        if (img0 + img < BATCH) {
            int px = r >> 3, q = r & 7;
            int y = px / 7, xx = px - y * 7;
            *reinterpret_cast<uint4*>(s_in + img * 9680 + ((y + 2) * 11 + (xx + 2)) * 80 + q * 8) =
                *reinterpret_cast<const uint4*>(g_a2 + ((img0 + img) * 49 + px) * 64 + q * 8);
        }
    }
    __syncthreads();

    // 16 m-tiles over 245 rows (img*49+px), one tile per warp; clamp pad rows
    int r0 = warp * 16 + gid, r1 = r0 + 8;
    int rc0 = r0 < 244 ? r0 : 244;
    int rc1 = r1 < 244 ? r1 : 244;
    int i0 = rc0 / 49, p0 = rc0 - i0 * 49;
    int i1 = rc1 / 49, p1 = rc1 - i1 * 49;
    int y0 = p0 / 7, x0 = p0 - y0 * 7;
    int y1 = p1 / 7, x1 = p1 - y1 * 7;
    const int aoff0 = i0 * 9680 + (y0 * 11 + x0) * 80 + kq;
    const int aoff1 = i1 * 9680 + (y1 * 11 + x1) * 80 + kq;

    float acc[4][4];
#pragma unroll
    for (int nt = 0; nt < 4; nt++)
#pragma unroll
        for (int j = 0; j < 4; j++) acc[nt][j] = 0.f;

    int wrb[4];
#pragma unroll
    for (int nt = 0; nt < 4; nt++) wrb[nt] = (nt * 8 + gid) * 1616 + kq;

#pragma unroll 1
    for (int s = 0; s < 50; s++) {
        const int off = s >> 1;
        const int iche = (s & 1) << 5;
        const int dpix = s_lut[off] + iche;
        const int wofs = off * 64 + iche;
        uint32_t bh0[4], bh1[4], bl0[4], bl1[4];
#pragma unroll
        for (int nt = 0; nt < 4; nt++) {
            uint2 w0 = lds_u64(s_w, wrb[nt] + wofs);
            uint2 w1 = lds_u64(s_w, wrb[nt] + wofs + 16);
            bh0[nt] = w0.x; bl0[nt] = w0.y;
            bh1[nt] = w1.x; bl1[nt] = w1.y;
        }
        int o0 = aoff0 + dpix;
        int o1 = aoff1 + dpix;
        uint2 a00 = lds_u64(s_in, o0);
        uint2 a01 = lds_u64(s_in, o1);
        uint2 a02 = lds_u64(s_in, o0 + 16);
        uint2 a03 = lds_u64(s_in, o1 + 16);
#pragma unroll
        for (int nt = 0; nt < 4; nt++)
            mma_bf16(acc[nt], a00.x, a01.x, a02.x, a03.x, bh0[nt], bh1[nt]);
#pragma unroll
        for (int nt = 0; nt < 4; nt++)
            mma_bf16(acc[nt], a00.x, a01.x, a02.x, a03.x, bl0[nt], bl1[nt]);
#pragma unroll
        for (int nt = 0; nt < 4; nt++)
            mma_bf16(acc[nt], a00.y, a01.y, a02.y, a03.y, bh0[nt], bh1[nt]);
    }

    // epilogue: bias + relu, pool (pad=1): pooled idx = ((y+1)/2)*4 + (x+1)/2
    {
        bool v0 = (r0 < 245) && (img0 + i0 < BATCH);
        bool v1 = (r1 < 245) && (img0 + i1 < BATCH);
        int pi0 = i0 * 512 + (((y0 + 1) >> 1) * 4 + ((x0 + 1) >> 1)) * 32;
        int pi1 = i1 * 512 + (((y1 + 1) >> 1) * 4 + ((x1 + 1) >> 1)) * 32;
#pragma unroll
        for (int nt = 0; nt < 4; nt++) {
            int col = nt * 8 + tg * 2;
            float bb0 = s_bias[col], bb1 = s_bias[col + 1];
            if (v0) {
                atomicMax(&s_pool[pi0 + col], __float_as_int(fmaxf(acc[nt][0] + bb0, 0.f)));
                atomicMax(&s_pool[pi0 + col + 1], __float_as_int(fmaxf(acc[nt][1] + bb1, 0.f)));
            }
            if (v1) {
                atomicMax(&s_pool[pi1 + col], __float_as_int(fmaxf(acc[nt][2] + bb0, 0.f)));
                atomicMax(&s_pool[pi1 + col + 1], __float_as_int(fmaxf(acc[nt][3] + bb1, 0.f)));
            }
        }
    }
    __syncthreads();
    // k = (g*32+ocl)*16 + pidx; pairs over pidx -> interleaved g_a3
    for (int i = tid; i < 1280; i += 512) {
        int img = i >> 8, r = i & 255;
        if (img0 + img < BATCH) {
            int ocl = r >> 3, pp = r & 7;
            float v0 = __int_as_float(s_pool[img * 512 + (2 * pp) * 32 + ocl]);
            float v1 = __int_as_float(s_pool[img * 512 + (2 * pp + 1) * 32 + ocl]);
            int gp = (g * 32 + ocl) * 8 + pp;
            *reinterpret_cast<uint2*>(g_a3 + (img0 + img) * 2048 + gp * 4) = pack4(v0, v1);
        }
    }
}

// ---------------- fc1 via bf16x3 MMA, interleaved LDS.64 ----------------
#define FC1_STRIDE 144
#define FC1_SMEM (2 * 128 * FC1_STRIDE * 2)
__global__ void __launch_bounds__(256) k_fc1(const float* __restrict__ bias) {
    extern __shared__ char smem[];
    __nv_bfloat16* s_a = (__nv_bfloat16*)smem;
    __nv_bfloat16* s_b = s_a + 128 * FC1_STRIDE;
    const int tid = threadIdx.x;
    const int warp = tid >> 5, lane = tid & 31;
    const int wm = warp >> 1, wn = warp & 1;
    const int m0 = blockIdx.y * 128, n0 = blockIdx.x * 128;
    const int gid = lane >> 2, tg = lane & 3;
    const int kq = tg * 4;

    float acc[2][8][4];
#pragma unroll
    for (int mt = 0; mt < 2; mt++)
#pragma unroll
        for (int nt = 0; nt < 8; nt++)
#pragma unroll
            for (int j = 0; j < 4; j++) acc[mt][nt][j] = 0.f;

#pragma unroll 1
    for (int k0e = 0; k0e < 2048; k0e += 128) {
        __syncthreads();
        for (int i = tid; i < 4096; i += 256) {
            int j = i & 2047;
            int row = j >> 4, q = j & 15;
            int dst = row * FC1_STRIDE + q * 8;
            if (i < 2048)
                *reinterpret_cast<uint4*>(s_a + dst) =
                    *reinterpret_cast<const uint4*>(g_a3 + (m0 + row) * 2048 + k0e + q * 8);
            else
                *reinterpret_cast<uint4*>(s_b + dst) =
                    *reinterpret_cast<const uint4*>(g_fw1 + (n0 + row) * 2048 + k0e + q * 8);
        }
        __syncthreads();
#pragma unroll
        for (int ks = 0; ks < 4; ks++) {
            int kb = ks * 32 + kq;
            uint32_t ah[2][4], al[2][4];
#pragma unroll
            for (int mt = 0; mt < 2; mt++) {
                int base = (wm * 32 + mt * 16 + gid) * FC1_STRIDE + kb;
                uint2 q0 = lds_u64(s_a, base);
                uint2 q1 = lds_u64(s_a, base + 8 * FC1_STRIDE);
                uint2 q2 = lds_u64(s_a, base + 16);
                uint2 q3 = lds_u64(s_a, base + 8 * FC1_STRIDE + 16);
                ah[mt][0] = q0.x; al[mt][0] = q0.y;
                ah[mt][1] = q1.x; al[mt][1] = q1.y;
                ah[mt][2] = q2.x; al[mt][2] = q2.y;
                ah[mt][3] = q3.x; al[mt][3] = q3.y;
            }
            uint32_t bh[8][2], bl[8][2];
#pragma unroll
            for (int nt = 0; nt < 8; nt++) {
                int base = (wn * 64 + nt * 8 + gid) * FC1_STRIDE + kb;
                uint2 w0 = lds_u64(s_b, base);
                uint2 w1 = lds_u64(s_b, base + 16);
                bh[nt][0] = w0.x; bl[nt][0] = w0.y;
                bh[nt][1] = w1.x; bl[nt][1] = w1.y;
            }
#pragma unroll
            for (int mt = 0; mt < 2; mt++) {
#pragma unroll
                for (int nt = 0; nt < 8; nt++)
                    mma_bf16(acc[mt][nt], ah[mt][0], ah[mt][1], ah[mt][2], ah[mt][3], bh[nt][0], bh[nt][1]);
#pragma unroll
                for (int nt = 0; nt < 8; nt++)
                    mma_bf16(acc[mt][nt], ah[mt][0], ah[mt][1], ah[mt][2], ah[mt][3], bl[nt][0], bl[nt][1]);
#pragma unroll
                for (int nt = 0; nt < 8; nt++)
                    mma_bf16(acc[mt][nt], al[mt][0], al[mt][1], al[mt][2], al[mt][3], bh[nt][0], bh[nt][1]);
            }
        }
    }
#pragma unroll
    for (int mt = 0; mt < 2; mt++) {
        int r = m0 + wm * 32 + mt * 16 + gid;
#pragma unroll
        for (int nt = 0; nt < 8; nt++) {
            int c = n0 + wn * 64 + nt * 8 + tg * 2;
            float b0 = bias[c], b1 = bias[c + 1];
            g_a4[r * 256 + c]           = fmaxf(acc[mt][nt][0] + b0, 0.f);
            g_a4[r * 256 + c + 1]       = fmaxf(acc[mt][nt][1] + b1, 0.f);
            g_a4[(r + 8) * 256 + c]     = fmaxf(acc[mt][nt][2] + b0, 0.f);
            g_a4[(r + 8) * 256 + c + 1] = fmaxf(acc[mt][nt][3] + b1, 0.f);
        }
    }
}

// ---------------- fc2 + log_softmax ----------------
__global__ void __launch_bounds__(256) k_fc2(const float* __restrict__ W,
                                             const float* __restrict__ bias,
                                             float* __restrict__ out) {
    __shared__ float s_w[2560];
    __shared__ float s_b[10];
    const int tid = threadIdx.x;
    for (int i = tid; i < 2560; i += 256) s_w[i] = W[i];
    if (tid < 10) s_b[tid] = bias[tid];
    __syncthreads();

    const int warp = tid >> 5, lane = tid & 31;
    const int row = blockIdx.x * 8 + warp;
    float hv[8];
    const float* hp = g_a4 + row * 256 + lane;
#pragma unroll
    for (int j = 0; j < 8; j++) hv[j] = hp[j * 32];

    float acc[10];
#pragma unroll
    for (int o = 0; o < 10; o++) acc[o] = 0.f;
#pragma unroll
    for (int j = 0; j < 8; j++) {
#pragma unroll
        for (int o = 0; o < 10; o++)
            acc[o] += hv[j] * s_w[o * 256 + lane + j * 32];
    }
#pragma unroll
    for (int o = 0; o < 10; o++) {
#pragma unroll
        for (int off = 16; off > 0; off >>= 1)
            acc[o] += __shfl_xor_sync(0xffffffffu, acc[o], off);
    }
    if (lane == 0) {
        float l[10], m = -1e30f;
#pragma unroll
        for (int o = 0; o < 10; o++) { l[o] = acc[o] + s_b[o]; m = fmaxf(m, l[o]); }
        float s = 0.f;
#pragma unroll
        for (int o = 0; o < 10; o++) s += expf(l[o] - m);
        float ls = logf(s);
        float* op = out + row * 10;
#pragma unroll
        for (int o = 0; o < 10; o++) op[o] = l[o] - m - ls;
    }
}

extern "C" void kernel_launch(void* const* d_in, const int* in_sizes, int n_in,
                              void* d_out, int out_size) {
    const float* x   = (const float*)d_in[0];
    const float* w1  = (const float*)d_in[1];
    const float* b1  = (const float*)d_in[2];
    const float* w2  = (const float*)d_in[3];
    const float* b2  = (const float*)d_in[4];
    const float* w3  = (const float*)d_in[5];
    const float* b3  = (const float*)d_in[6];
    const float* fw1 = (const float*)d_in[7];
    const float* fb1 = (const float*)d_in[8];
    const float* fw2 = (const float*)d_in[9];
    const float* fb2 = (const float*)d_in[10];
    float* out = (float*)d_out;

    cudaFuncSetAttribute(k_conv2, cudaFuncAttributeMaxDynamicSharedMemorySize, C2_SMEM);
    cudaFuncSetAttribute(k_conv3, cudaFuncAttributeMaxDynamicSharedMemorySize, C3_SMEM);
    cudaFuncSetAttribute(k_fc1,   cudaFuncAttributeMaxDynamicSharedMemorySize, FC1_SMEM);

    k_prep_fc1<<<512, 256>>>(fw1);
    k_prep_w2<<<25, 256>>>(w2);
    k_prep_w3<<<100, 256>>>(w3);
    k_conv1<<<BATCH, 784>>>(x, w1, b1);
    k_conv2<<<BATCH / 4, 512, C2_SMEM>>>(b2);
    k_conv3<<<dim3((BATCH + 4) / 5, 2), 512, C3_SMEM>>>(b3);
    k_fc1<<<dim3(2, BATCH / 128), 256, FC1_SMEM>>>(fb1);
    k_fc2<<<BATCH / 8, 256>>>(fw2, fb2, out);
}

// round 8
// speedup vs baseline: 1.6086x; 1.1380x over previous
#include <cuda_runtime.h>
#include <cuda_bf16.h>
#include <math.h>
#include <stdint.h>

#define BATCH 8192

// Activations / weights in gmem, bf16 hi/lo interleaved in groups of 4:
//   group p (4 elems): [hi(2p), hi(2p+1), lo(2p), lo(2p+1)]
__device__ __nv_bfloat16 g_a1[BATCH * 196 * 32];   // conv1 out: [b][px][16ic -> 32 elem]
__device__ __nv_bfloat16 g_a2[BATCH * 49 * 64];    // conv2 out: [b][px][32ic -> 64 elem]
__device__ __nv_bfloat16 g_a3[BATCH * 2048];       // conv3 out: [b][1024k -> 2048 elem]
__device__ float g_a4[BATCH * 256];                // fc1 out
__device__ __nv_bfloat16 g_fw1[256 * 2048];        // fc1 W interleaved
__device__ __nv_bfloat16 g_w2i[32 * 800];          // conv2 W: [oc][off*32 + p*4]
__device__ __nv_bfloat16 g_w3i[64 * 1600];         // conv3 W: [oc][off*64 + p*4]

__device__ __forceinline__ uint16_t bfbits(__nv_bfloat16 x) {
    return *reinterpret_cast<uint16_t*>(&x);
}
__device__ __forceinline__ void bf16split(float v, __nv_bfloat16& h, __nv_bfloat16& l) {
    h = __float2bfloat16(v);
    l = __float2bfloat16(v - __bfloat162float(h));
}
__device__ __forceinline__ uint2 pack4(float v0, float v1) {
    __nv_bfloat16 h0, l0, h1, l1;
    bf16split(v0, h0, l0);
    bf16split(v1, h1, l1);
    uint2 r;
    r.x = (uint32_t)bfbits(h0) | ((uint32_t)bfbits(h1) << 16);
    r.y = (uint32_t)bfbits(l0) | ((uint32_t)bfbits(l1) << 16);
    return r;
}

__device__ __forceinline__ void mma_bf16(float* c,
                                         uint32_t a0, uint32_t a1, uint32_t a2, uint32_t a3,
                                         uint32_t b0, uint32_t b1) {
    asm volatile(
        "mma.sync.aligned.m16n8k16.row.col.f32.bf16.bf16.f32 "
        "{%0,%1,%2,%3}, {%4,%5,%6,%7}, {%8,%9}, {%0,%1,%2,%3};"
        : "+f"(c[0]), "+f"(c[1]), "+f"(c[2]), "+f"(c[3])
        : "r"(a0), "r"(a1), "r"(a2), "r"(a3), "r"(b0), "r"(b1));
}

__device__ __forceinline__ uint2 lds_u64(const __nv_bfloat16* p, int elem_idx) {
    return *reinterpret_cast<const uint2*>(p + elem_idx);
}

// cp.async helpers (16B)
__device__ __forceinline__ void cp16(void* smem_dst, const void* gmem_src) {
    uint32_t d = (uint32_t)__cvta_generic_to_shared(smem_dst);
    asm volatile("cp.async.cg.shared.global [%0], [%1], 16;\n" :: "r"(d), "l"(gmem_src));
}
#define CP_COMMIT() asm volatile("cp.async.commit_group;\n" ::: "memory")
#define CP_WAIT(n)  asm volatile("cp.async.wait_group %0;\n" :: "n"(n) : "memory")

// ---------------- prep kernels ----------------
__global__ void __launch_bounds__(256) k_prep_fc1(const float* __restrict__ fw1) {
    int i = blockIdx.x * 256 + threadIdx.x;
    int row = i >> 9, p = i & 511;
    uint2 v = pack4(fw1[row * 1024 + 2 * p], fw1[row * 1024 + 2 * p + 1]);
    *reinterpret_cast<uint2*>(g_fw1 + row * 2048 + p * 4) = v;
}
__global__ void __launch_bounds__(256) k_prep_w2(const float* __restrict__ w2) {
    int i = blockIdx.x * 256 + threadIdx.x;
    if (i >= 6400) return;
    int oc = i / 200, r = i - oc * 200;
    int off = r >> 3, p = r & 7;
    uint2 v = pack4(w2[oc * 400 + (2 * p) * 25 + off], w2[oc * 400 + (2 * p + 1) * 25 + off]);
    *reinterpret_cast<uint2*>(g_w2i + oc * 800 + off * 32 + p * 4) = v;
}
__global__ void __launch_bounds__(256) k_prep_w3(const float* __restrict__ w3) {
    int i = blockIdx.x * 256 + threadIdx.x;
    int oc = i / 400, r = i - oc * 400;
    int off = r >> 4, p = r & 15;
    uint2 v = pack4(w3[oc * 800 + (2 * p) * 25 + off], w3[oc * 800 + (2 * p + 1) * 25 + off]);
    *reinterpret_cast<uint2*>(g_w3i + oc * 1600 + off * 64 + p * 4) = v;
}

// ---------------- conv1 (1->16) FFMA + relu + pool (R5 form) ----------------
__global__ void __launch_bounds__(784) k_conv1(const float* __restrict__ x,
                                               const float* __restrict__ w1,
                                               const float* __restrict__ b1) {
    __shared__ float s_in[32 * 33];
    __shared__ float s_w[400];
    __shared__ float s_b[16];
    const int img = blockIdx.x;
    const int tid = threadIdx.x;

    if (tid < 400) s_w[tid] = w1[tid];
    if (tid < 16) s_b[tid] = b1[tid];
    for (int i = tid; i < 32 * 33; i += 784) s_in[i] = 0.f;
    __syncthreads();
    {
        int r = tid / 28, c = tid - r * 28;
        s_in[(r + 2) * 33 + (c + 2)] = x[img * 784 + tid];
    }
    __syncthreads();

    const int ocq = tid / 196;
    const int sp  = tid - ocq * 196;
    const int py = sp / 14, px = sp - py * 14;
    const int y0 = 2 * py, x0 = 2 * px;

    float acc[4][4];
#pragma unroll
    for (int j = 0; j < 4; j++) {
        float bv = s_b[ocq * 4 + j];
        acc[j][0] = bv; acc[j][1] = bv; acc[j][2] = bv; acc[j][3] = bv;
    }
    const float* wb = s_w + ocq * 100;
#pragma unroll
    for (int ky = 0; ky < 5; ky++) {
        const float* r0 = &s_in[(y0 + ky) * 33 + x0];
        const float* r1 = r0 + 33;
#pragma unroll
        for (int kx = 0; kx < 5; kx++) {
            float i0 = r0[kx], i1 = r0[kx + 1], i2 = r1[kx], i3 = r1[kx + 1];
#pragma unroll
            for (int j = 0; j < 4; j++) {
                float wv = wb[j * 25 + ky * 5 + kx];
                acc[j][0] += wv * i0; acc[j][1] += wv * i1;
                acc[j][2] += wv * i2; acc[j][3] += wv * i3;
            }
        }
    }
    float m[4];
#pragma unroll
    for (int j = 0; j < 4; j++)
        m[j] = fmaxf(fmaxf(fmaxf(acc[j][0], acc[j][1]), fmaxf(acc[j][2], acc[j][3])), 0.f);
    __nv_bfloat16* dst = g_a1 + (img * 196 + sp) * 32;
    *reinterpret_cast<uint2*>(dst + (ocq * 2 + 0) * 4) = pack4(m[0], m[1]);
    *reinterpret_cast<uint2*>(dst + (ocq * 2 + 1) * 4) = pack4(m[2], m[3]);
}

// ---------------- conv2 (16->32): 4 img/block, 512 thr, cp.async fills ----------------
#define C2_SMEM 201984
__global__ void __launch_bounds__(512) k_conv2(const float* __restrict__ b2) {
    extern __shared__ char smem[];
    __nv_bfloat16* s_in = (__nv_bfloat16*)(smem);               // 62208 elem
    __nv_bfloat16* s_w  = (__nv_bfloat16*)(smem + 124416);      // 26112 elem
    int*           s_pool = (int*)(smem + 176640);              // 6272 int
    float*         s_bias = (float*)(smem + 201728);
    int*           s_lut  = (int*)(smem + 201856);              // 25

    const int img0 = blockIdx.x * 4;
    const int tid = threadIdx.x;
    const int warp = tid >> 5;
    const int lane = tid & 31;
    const int gid = lane >> 2;
    const int tg  = lane & 3;
    const int kq  = tg * 4;

    uint4 z4 = {0, 0, 0, 0};
    for (int i = tid; i < 7776; i += 512) ((uint4*)s_in)[i] = z4;
    for (int i = tid; i < 6272; i += 512) s_pool[i] = 0;
    if (tid < 32) s_bias[tid] = b2[tid];
    if (tid < 25) { int dy = tid / 5, dx = tid - dy * 5; s_lut[tid] = (dy * 18 + dx) * 48; }
    __syncthreads();   // zeros visible before cp.async overwrites interior
    for (int i = tid; i < 3200; i += 512) {
        int oc = i / 100, r = i - oc * 100;
        cp16(s_w + oc * 816 + r * 8, g_w2i + oc * 800 + r * 8);
    }
    for (int i = tid; i < 3136; i += 512) {
        int img = i / 784, r = i - img * 784;
        int px = r >> 2, q = r & 3;
        int y = px / 14, xx = px - y * 14;
        cp16(s_in + img * 15552 + ((y + 2) * 18 + (xx + 2)) * 48 + q * 8,
             g_a1 + ((img0 + img) * 196 + px) * 32 + q * 8);
    }
    CP_COMMIT();
    CP_WAIT(0);
    __syncthreads();

    int aoff0[4], aoff1[4];
#pragma unroll
    for (int ti = 0; ti < 4; ti++) {
        int t = warp + 16 * ti;
        if (t < 49) {
            int r0 = t * 16 + gid, r1 = r0 + 8;
            int i0 = r0 / 196, p0 = r0 - i0 * 196;
            int i1 = r1 / 196, p1 = r1 - i1 * 196;
            int y0 = p0 / 14, x0 = p0 - y0 * 14;
            int y1 = p1 / 14, x1 = p1 - y1 * 14;
            aoff0[ti] = i0 * 15552 + (y0 * 18 + x0) * 48 + kq;
            aoff1[ti] = i1 * 15552 + (y1 * 18 + x1) * 48 + kq;
        }
    }

    float acc[4][4][4];
#pragma unroll
    for (int ti = 0; ti < 4; ti++)
#pragma unroll
        for (int nt = 0; nt < 4; nt++)
#pragma unroll
            for (int j = 0; j < 4; j++) acc[ti][nt][j] = 0.f;

    int wrb[4];
#pragma unroll
    for (int nt = 0; nt < 4; nt++) wrb[nt] = (nt * 8 + gid) * 816 + kq;

#pragma unroll 1
    for (int off = 0; off < 25; off++) {
        const int dpix = s_lut[off];
        const int wofs = off * 32;
        uint32_t bh0[4], bh1[4], bl0[4], bl1[4];
#pragma unroll
        for (int nt = 0; nt < 4; nt++) {
            uint2 w0 = lds_u64(s_w, wrb[nt] + wofs);
            uint2 w1 = lds_u64(s_w, wrb[nt] + wofs + 16);
            bh0[nt] = w0.x; bl0[nt] = w0.y;
            bh1[nt] = w1.x; bl1[nt] = w1.y;
        }
#pragma unroll
        for (int ti = 0; ti < 4; ti++) {
            int t = warp + 16 * ti;
            if (t < 49) {
                int o0 = aoff0[ti] + dpix;
                int o1 = aoff1[ti] + dpix;
                uint2 a00 = lds_u64(s_in, o0);
                uint2 a01 = lds_u64(s_in, o1);
                uint2 a02 = lds_u64(s_in, o0 + 16);
                uint2 a03 = lds_u64(s_in, o1 + 16);
#pragma unroll
                for (int nt = 0; nt < 4; nt++)
                    mma_bf16(acc[ti][nt], a00.x, a01.x, a02.x, a03.x, bh0[nt], bh1[nt]);
#pragma unroll
                for (int nt = 0; nt < 4; nt++)
                    mma_bf16(acc[ti][nt], a00.x, a01.x, a02.x, a03.x, bl0[nt], bl1[nt]);
#pragma unroll
                for (int nt = 0; nt < 4; nt++)
                    mma_bf16(acc[ti][nt], a00.y, a01.y, a02.y, a03.y, bh0[nt], bh1[nt]);
            }
        }
    }

#pragma unroll
    for (int ti = 0; ti < 4; ti++) {
        int t = warp + 16 * ti;
        if (t < 49) {
            int r0 = t * 16 + gid, r1 = r0 + 8;
            int i0 = r0 / 196, p0 = r0 - i0 * 196;
            int i1 = r1 / 196, p1 = r1 - i1 * 196;
            int y0 = p0 / 14, x0 = p0 - y0 * 14;
            int y1 = p1 / 14, x1 = p1 - y1 * 14;
            int pi0 = i0 * 1568 + ((y0 >> 1) * 7 + (x0 >> 1)) * 32;
            int pi1 = i1 * 1568 + ((y1 >> 1) * 7 + (x1 >> 1)) * 32;
#pragma unroll
            for (int nt = 0; nt < 4; nt++) {
                int col = nt * 8 + tg * 2;
                float bb0 = s_bias[col], bb1 = s_bias[col + 1];
                atomicMax(&s_pool[pi0 + col], __float_as_int(fmaxf(acc[ti][nt][0] + bb0, 0.f)));
                atomicMax(&s_pool[pi0 + col + 1], __float_as_int(fmaxf(acc[ti][nt][1] + bb1, 0.f)));
                atomicMax(&s_pool[pi1 + col], __float_as_int(fmaxf(acc[ti][nt][2] + bb0, 0.f)));
                atomicMax(&s_pool[pi1 + col + 1], __float_as_int(fmaxf(acc[ti][nt][3] + bb1, 0.f)));
            }
        }
    }
    __syncthreads();
    for (int i = tid; i < 3136; i += 512) {
        int img = i / 784, r = i - img * 784;
        int px = r >> 4, p = r & 15;
        float v0 = __int_as_float(s_pool[img * 1568 + px * 32 + 2 * p]);
        float v1 = __int_as_float(s_pool[img * 1568 + px * 32 + 2 * p + 1]);
        *reinterpret_cast<uint2*>(g_a2 + ((img0 + img) * 49 + px) * 64 + p * 4) = pack4(v0, v1);
    }
}

// ---------------- conv3 (32->64): 5 img/block, 512 thr, cp.async fills ----------------
#define C3_SMEM 210720
__global__ void __launch_bounds__(512) k_conv3(const float* __restrict__ b3) {
    extern __shared__ char smem[];
    __nv_bfloat16* s_in = (__nv_bfloat16*)(smem);               // 48400 elem
    __nv_bfloat16* s_w  = (__nv_bfloat16*)(smem + 96800);       // 51712 elem
    int*           s_pool = (int*)(smem + 200224);              // 2560 int
    float*         s_bias = (float*)(smem + 210464);
    int*           s_lut  = (int*)(smem + 210592);              // 25

    const int img0 = blockIdx.x * 5;
    const int g = blockIdx.y;
    const int tid = threadIdx.x;
    const int warp = tid >> 5;
    const int lane = tid & 31;
    const int gid = lane >> 2;
    const int tg  = lane & 3;
    const int kq  = tg * 4;

    uint4 z4 = {0, 0, 0, 0};
    for (int i = tid; i < 6050; i += 512) ((uint4*)s_in)[i] = z4;
    for (int i = tid; i < 2560; i += 512) s_pool[i] = 0;
    if (tid < 32) s_bias[tid] = b3[g * 32 + tid];
    if (tid < 25) { int dy = tid / 5, dx = tid - dy * 5; s_lut[tid] = (dy * 11 + dx) * 80; }
    __syncthreads();
    const __nv_bfloat16* wg = g_w3i + g * 32 * 1600;
    for (int i = tid; i < 6400; i += 512) {
        int ocl = i / 200, r = i - ocl * 200;
        cp16(s_w + ocl * 1616 + r * 8, wg + ocl * 1600 + r * 8);
    }
    for (int i = tid; i < 1960; i += 512) {
        int img = i / 392, r = i - img * 392;
        if (img0 + img < BATCH) {
            int px = r >> 3, q = r & 7;
            int y = px / 7, xx = px - y * 7;
            cp16(s_in + img * 9680 + ((y + 2) * 11 + (xx + 2)) * 80 + q * 8,
                 g_a2 + ((img0 + img) * 49 + px) * 64 + q * 8);
        }
    }
    CP_COMMIT();
    CP_WAIT(0);
    __syncthreads();

    int r0 = warp * 16 + gid, r1 = r0 + 8;
    int rc0 = r0 < 244 ? r0 : 244;
    int rc1 = r1 < 244 ? r1 : 244;
    int i0 = rc0 / 49, p0 = rc0 - i0 * 49;
    int i1 = rc1 / 49, p1 = rc1 - i1 * 49;
    int y0 = p0 / 7, x0 = p0 - y0 * 7;
    int y1 = p1 / 7, x1 = p1 - y1 * 7;
    const int aoff0 = i0 * 9680 + (y0 * 11 + x0) * 80 + kq;
    const int aoff1 = i1 * 9680 + (y1 * 11 + x1) * 80 + kq;

    float acc[4][4];
#pragma unroll
    for (int nt = 0; nt < 4; nt++)
#pragma unroll
        for (int j = 0; j < 4; j++) acc[nt][j] = 0.f;

    int wrb[4];
#pragma unroll
    for (int nt = 0; nt < 4; nt++) wrb[nt] = (nt * 8 + gid) * 1616 + kq;

#pragma unroll 1
    for (int s = 0; s < 50; s++) {
        const int off = s >> 1;
        const int iche = (s & 1) << 5;
        const int dpix = s_lut[off] + iche;
        const int wofs = off * 64 + iche;
        uint32_t bh0[4], bh1[4], bl0[4], bl1[4];
#pragma unroll
        for (int nt = 0; nt < 4; nt++) {
            uint2 w0 = lds_u64(s_w, wrb[nt] + wofs);
            uint2 w1 = lds_u64(s_w, wrb[nt] + wofs + 16);
            bh0[nt] = w0.x; bl0[nt] = w0.y;
            bh1[nt] = w1.x; bl1[nt] = w1.y;
        }
        int o0 = aoff0 + dpix;
        int o1 = aoff1 + dpix;
        uint2 a00 = lds_u64(s_in, o0);
        uint2 a01 = lds_u64(s_in, o1);
        uint2 a02 = lds_u64(s_in, o0 + 16);
        uint2 a03 = lds_u64(s_in, o1 + 16);
#pragma unroll
        for (int nt = 0; nt < 4; nt++)
            mma_bf16(acc[nt], a00.x, a01.x, a02.x, a03.x, bh0[nt], bh1[nt]);
#pragma unroll
        for (int nt = 0; nt < 4; nt++)
            mma_bf16(acc[nt], a00.x, a01.x, a02.x, a03.x, bl0[nt], bl1[nt]);
#pragma unroll
        for (int nt = 0; nt < 4; nt++)
            mma_bf16(acc[nt], a00.y, a01.y, a02.y, a03.y, bh0[nt], bh1[nt]);
    }

    {
        bool v0 = (r0 < 245) && (img0 + i0 < BATCH);
        bool v1 = (r1 < 245) && (img0 + i1 < BATCH);
        int pi0 = i0 * 512 + (((y0 + 1) >> 1) * 4 + ((x0 + 1) >> 1)) * 32;
        int pi1 = i1 * 512 + (((y1 + 1) >> 1) * 4 + ((x1 + 1) >> 1)) * 32;
#pragma unroll
        for (int nt = 0; nt < 4; nt++) {
            int col = nt * 8 + tg * 2;
            float bb0 = s_bias[col], bb1 = s_bias[col + 1];
            if (v0) {
                atomicMax(&s_pool[pi0 + col], __float_as_int(fmaxf(acc[nt][0] + bb0, 0.f)));
                atomicMax(&s_pool[pi0 + col + 1], __float_as_int(fmaxf(acc[nt][1] + bb1, 0.f)));
            }
            if (v1) {
                atomicMax(&s_pool[pi1 + col], __float_as_int(fmaxf(acc[nt][2] + bb0, 0.f)));
                atomicMax(&s_pool[pi1 + col + 1], __float_as_int(fmaxf(acc[nt][3] + bb1, 0.f)));
            }
        }
    }
    __syncthreads();
    for (int i = tid; i < 1280; i += 512) {
        int img = i >> 8, r = i & 255;
        if (img0 + img < BATCH) {
            int ocl = r >> 3, pp = r & 7;
            float v0 = __int_as_float(s_pool[img * 512 + (2 * pp) * 32 + ocl]);
            float v1 = __int_as_float(s_pool[img * 512 + (2 * pp + 1) * 32 + ocl]);
            int gp = (g * 32 + ocl) * 8 + pp;
            *reinterpret_cast<uint2*>(g_a3 + (img0 + img) * 2048 + gp * 4) = pack4(v0, v1);
        }
    }
}

// ---------------- fc1 via bf16x3 MMA, cp.async double-buffered ----------------
#define FC1_STRIDE 144
#define FC1_STAGE (128 * FC1_STRIDE)           // elems per operand per stage
#define FC1_SMEM (4 * FC1_STAGE * 2)           // 2 stages x (A+B) = 147456 B
__global__ void __launch_bounds__(256) k_fc1(const float* __restrict__ bias) {
    extern __shared__ char smem[];
    __nv_bfloat16* s_base = (__nv_bfloat16*)smem;
    const int tid = threadIdx.x;
    const int warp = tid >> 5, lane = tid & 31;
    const int wm = warp >> 1, wn = warp & 1;
    const int m0 = blockIdx.y * 128, n0 = blockIdx.x * 128;
    const int gid = lane >> 2, tg = lane & 3;
    const int kq = tg * 4;

    float acc[2][8][4];
#pragma unroll
    for (int mt = 0; mt < 2; mt++)
#pragma unroll
        for (int nt = 0; nt < 8; nt++)
#pragma unroll
            for (int j = 0; j < 4; j++) acc[mt][nt][j] = 0.f;

    // loader: 4096 cp16 per stage (A 2048 + B 2048), 16 per thread
    auto load_stage = [&](int stage, int k0e) {
        __nv_bfloat16* s_a = s_base + stage * 2 * FC1_STAGE;
        __nv_bfloat16* s_b = s_a + FC1_STAGE;
        for (int i = tid; i < 4096; i += 256) {
            int j = i & 2047;
            int row = j >> 4, q = j & 15;
            int dst = row * FC1_STRIDE + q * 8;
            if (i < 2048)
                cp16(s_a + dst, g_a3 + (m0 + row) * 2048 + k0e + q * 8);
            else
                cp16(s_b + dst, g_fw1 + (n0 + row) * 2048 + k0e + q * 8);
        }
        CP_COMMIT();
    };

    load_stage(0, 0);

#pragma unroll 1
    for (int k = 0; k < 16; k++) {
        if (k < 15) load_stage((k + 1) & 1, (k + 1) * 128);
        if (k < 15) { CP_WAIT(1); } else { CP_WAIT(0); }
        __syncthreads();
        __nv_bfloat16* s_a = s_base + (k & 1) * 2 * FC1_STAGE;
        __nv_bfloat16* s_b = s_a + FC1_STAGE;
#pragma unroll
        for (int ks = 0; ks < 4; ks++) {
            int kb = ks * 32 + kq;
            uint32_t ah[2][4], al[2][4];
#pragma unroll
            for (int mt = 0; mt < 2; mt++) {
                int base = (wm * 32 + mt * 16 + gid) * FC1_STRIDE + kb;
                uint2 q0 = lds_u64(s_a, base);
                uint2 q1 = lds_u64(s_a, base + 8 * FC1_STRIDE);
                uint2 q2 = lds_u64(s_a, base + 16);
                uint2 q3 = lds_u64(s_a, base + 8 * FC1_STRIDE + 16);
                ah[mt][0] = q0.x; al[mt][0] = q0.y;
                ah[mt][1] = q1.x; al[mt][1] = q1.y;
                ah[mt][2] = q2.x; al[mt][2] = q2.y;
                ah[mt][3] = q3.x; al[mt][3] = q3.y;
            }
            uint32_t bh[8][2], bl[8][2];
#pragma unroll
            for (int nt = 0; nt < 8; nt++) {
                int base = (wn * 64 + nt * 8 + gid) * FC1_STRIDE + kb;
                uint2 w0 = lds_u64(s_b, base);
                uint2 w1 = lds_u64(s_b, base + 16);
                bh[nt][0] = w0.x; bl[nt][0] = w0.y;
                bh[nt][1] = w1.x; bl[nt][1] = w1.y;
            }
#pragma unroll
            for (int mt = 0; mt < 2; mt++) {
#pragma unroll
                for (int nt = 0; nt < 8; nt++)
                    mma_bf16(acc[mt][nt], ah[mt][0], ah[mt][1], ah[mt][2], ah[mt][3], bh[nt][0], bh[nt][1]);
#pragma unroll
                for (int nt = 0; nt < 8; nt++)
                    mma_bf16(acc[mt][nt], ah[mt][0], ah[mt][1], ah[mt][2], ah[mt][3], bl[nt][0], bl[nt][1]);
#pragma unroll
                for (int nt = 0; nt < 8; nt++)
                    mma_bf16(acc[mt][nt], al[mt][0], al[mt][1], al[mt][2], al[mt][3], bh[nt][0], bh[nt][1]);
            }
        }
        __syncthreads();
    }
#pragma unroll
    for (int mt = 0; mt < 2; mt++) {
        int r = m0 + wm * 32 + mt * 16 + gid;
#pragma unroll
        for (int nt = 0; nt < 8; nt++) {
            int c = n0 + wn * 64 + nt * 8 + tg * 2;
            float b0 = bias[c], b1 = bias[c + 1];
            g_a4[r * 256 + c]           = fmaxf(acc[mt][nt][0] + b0, 0.f);
            g_a4[r * 256 + c + 1]       = fmaxf(acc[mt][nt][1] + b1, 0.f);
            g_a4[(r + 8) * 256 + c]     = fmaxf(acc[mt][nt][2] + b0, 0.f);
            g_a4[(r + 8) * 256 + c + 1] = fmaxf(acc[mt][nt][3] + b1, 0.f);
        }
    }
}

// ---------------- fc2 + log_softmax ----------------
__global__ void __launch_bounds__(256) k_fc2(const float* __restrict__ W,
                                             const float* __restrict__ bias,
                                             float* __restrict__ out) {
    __shared__ float s_w[2560];
    __shared__ float s_b[10];
    const int tid = threadIdx.x;
    for (int i = tid; i < 2560; i += 256) s_w[i] = W[i];
    if (tid < 10) s_b[tid] = bias[tid];
    __syncthreads();

    const int warp = tid >> 5, lane = tid & 31;
    const int row = blockIdx.x * 8 + warp;
    float hv[8];
    const float* hp = g_a4 + row * 256 + lane;
#pragma unroll
    for (int j = 0; j < 8; j++) hv[j] = hp[j * 32];

    float acc[10];
#pragma unroll
    for (int o = 0; o < 10; o++) acc[o] = 0.f;
#pragma unroll
    for (int j = 0; j < 8; j++) {
#pragma unroll
        for (int o = 0; o < 10; o++)
            acc[o] += hv[j] * s_w[o * 256 + lane + j * 32];
    }
#pragma unroll
    for (int o = 0; o < 10; o++) {
#pragma unroll
        for (int off = 16; off > 0; off >>= 1)
            acc[o] += __shfl_xor_sync(0xffffffffu, acc[o], off);
    }
    if (lane == 0) {
        float l[10], m = -1e30f;
#pragma unroll
        for (int o = 0; o < 10; o++) { l[o] = acc[o] + s_b[o]; m = fmaxf(m, l[o]); }
        float s = 0.f;
#pragma unroll
        for (int o = 0; o < 10; o++) s += expf(l[o] - m);
        float ls = logf(s);
        float* op = out + row * 10;
#pragma unroll
        for (int o = 0; o < 10; o++) op[o] = l[o] - m - ls;
    }
}

extern "C" void kernel_launch(void* const* d_in, const int* in_sizes, int n_in,
                              void* d_out, int out_size) {
    const float* x   = (const float*)d_in[0];
    const float* w1  = (const float*)d_in[1];
    const float* b1  = (const float*)d_in[2];
    const float* w2  = (const float*)d_in[3];
    const float* b2  = (const float*)d_in[4];
    const float* w3  = (const float*)d_in[5];
    const float* b3  = (const float*)d_in[6];
    const float* fw1 = (const float*)d_in[7];
    const float* fb1 = (const float*)d_in[8];
    const float* fw2 = (const float*)d_in[9];
    const float* fb2 = (const float*)d_in[10];
    float* out = (float*)d_out;

    cudaFuncSetAttribute(k_conv2, cudaFuncAttributeMaxDynamicSharedMemorySize, C2_SMEM);
    cudaFuncSetAttribute(k_conv3, cudaFuncAttributeMaxDynamicSharedMemorySize, C3_SMEM);
    cudaFuncSetAttribute(k_fc1,   cudaFuncAttributeMaxDynamicSharedMemorySize, FC1_SMEM);

    k_prep_fc1<<<512, 256>>>(fw1);
    k_prep_w2<<<25, 256>>>(w2);
    k_prep_w3<<<100, 256>>>(w3);
    k_conv1<<<BATCH, 784>>>(x, w1, b1);
    k_conv2<<<BATCH / 4, 512, C2_SMEM>>>(b2);
    k_conv3<<<dim3((BATCH + 4) / 5, 2), 512, C3_SMEM>>>(b3);
    k_fc1<<<dim3(2, BATCH / 128), 256, FC1_SMEM>>>(fb1);
    k_fc2<<<BATCH / 8, 256>>>(fw2, fb2, out);
}

// round 9
// speedup vs baseline: 1.7078x; 1.0617x over previous
#include <cuda_runtime.h>
#include <cuda_bf16.h>
#include <math.h>
#include <stdint.h>

#define BATCH 8192

// Activations / weights in gmem, bf16 hi/lo interleaved in groups of 4:
//   group p (4 elems): [hi(2p), hi(2p+1), lo(2p), lo(2p+1)]
__device__ __nv_bfloat16 g_a1[BATCH * 196 * 32];   // conv1 out: [b][px][16ic -> 32 elem]
__device__ __nv_bfloat16 g_a2[BATCH * 49 * 64];    // conv2 out: [b][px][32ic -> 64 elem]
__device__ __nv_bfloat16 g_a3[BATCH * 2048];       // conv3 out: [b][1024k -> 2048 elem]
__device__ float g_a4[BATCH * 256];                // fc1 out
__device__ __nv_bfloat16 g_fw1[256 * 2048];        // fc1 W interleaved
__device__ __nv_bfloat16 g_w2i[32 * 800];          // conv2 W: [oc][off*32 + p*4]
__device__ __nv_bfloat16 g_w3i[64 * 1600];         // conv3 W: [oc][off*64 + p*4]

__device__ __forceinline__ uint16_t bfbits(__nv_bfloat16 x) {
    return *reinterpret_cast<uint16_t*>(&x);
}
__device__ __forceinline__ void bf16split(float v, __nv_bfloat16& h, __nv_bfloat16& l) {
    h = __float2bfloat16(v);
    l = __float2bfloat16(v - __bfloat162float(h));
}
__device__ __forceinline__ uint2 pack4(float v0, float v1) {
    __nv_bfloat16 h0, l0, h1, l1;
    bf16split(v0, h0, l0);
    bf16split(v1, h1, l1);
    uint2 r;
    r.x = (uint32_t)bfbits(h0) | ((uint32_t)bfbits(h1) << 16);
    r.y = (uint32_t)bfbits(l0) | ((uint32_t)bfbits(l1) << 16);
    return r;
}

__device__ __forceinline__ void mma_bf16(float* c,
                                         uint32_t a0, uint32_t a1, uint32_t a2, uint32_t a3,
                                         uint32_t b0, uint32_t b1) {
    asm volatile(
        "mma.sync.aligned.m16n8k16.row.col.f32.bf16.bf16.f32 "
        "{%0,%1,%2,%3}, {%4,%5,%6,%7}, {%8,%9}, {%0,%1,%2,%3};"
        : "+f"(c[0]), "+f"(c[1]), "+f"(c[2]), "+f"(c[3])
        : "r"(a0), "r"(a1), "r"(a2), "r"(a3), "r"(b0), "r"(b1));
}

__device__ __forceinline__ uint2 lds_u64(const __nv_bfloat16* p, int elem_idx) {
    return *reinterpret_cast<const uint2*>(p + elem_idx);
}
__device__ __forceinline__ uint32_t lds_u16(const __nv_bfloat16* p, int elem_idx) {
    return (uint32_t)*reinterpret_cast<const uint16_t*>(p + elem_idx);
}
__device__ __forceinline__ uint32_t pk(uint32_t lo, uint32_t hi) {
    return lo | (hi << 16);
}

// cp.async helpers (16B)
__device__ __forceinline__ void cp16(void* smem_dst, const void* gmem_src) {
    uint32_t d = (uint32_t)__cvta_generic_to_shared(smem_dst);
    asm volatile("cp.async.cg.shared.global [%0], [%1], 16;\n" :: "r"(d), "l"(gmem_src));
}
#define CP_COMMIT() asm volatile("cp.async.commit_group;\n" ::: "memory")
#define CP_WAIT(n)  asm volatile("cp.async.wait_group %0;\n" :: "n"(n) : "memory")

// ---------------- prep kernels ----------------
__global__ void __launch_bounds__(256) k_prep_fc1(const float* __restrict__ fw1) {
    int i = blockIdx.x * 256 + threadIdx.x;
    int row = i >> 9, p = i & 511;
    uint2 v = pack4(fw1[row * 1024 + 2 * p], fw1[row * 1024 + 2 * p + 1]);
    *reinterpret_cast<uint2*>(g_fw1 + row * 2048 + p * 4) = v;
}
__global__ void __launch_bounds__(256) k_prep_w2(const float* __restrict__ w2) {
    int i = blockIdx.x * 256 + threadIdx.x;
    if (i >= 6400) return;
    int oc = i / 200, r = i - oc * 200;
    int off = r >> 3, p = r & 7;
    uint2 v = pack4(w2[oc * 400 + (2 * p) * 25 + off], w2[oc * 400 + (2 * p + 1) * 25 + off]);
    *reinterpret_cast<uint2*>(g_w2i + oc * 800 + off * 32 + p * 4) = v;
}
__global__ void __launch_bounds__(256) k_prep_w3(const float* __restrict__ w3) {
    int i = blockIdx.x * 256 + threadIdx.x;
    int oc = i / 400, r = i - oc * 400;
    int off = r >> 4, p = r & 15;
    uint2 v = pack4(w3[oc * 800 + (2 * p) * 25 + off], w3[oc * 800 + (2 * p + 1) * 25 + off]);
    *reinterpret_cast<uint2*>(g_w3i + oc * 1600 + off * 64 + p * 4) = v;
}

// ---------------- conv1 (1->16) via bf16x3 MMA, implicit im2col ----------------
// 4 img/block, 512 thr (16 warps), M = 4*784 rows = 196 tiles, N=16, K=32 (25 real).
// Pad k>=25 handled by ZERO B rows; A reads may hit in-smem garbage (x0 = 0).
// smem: s_hi 4*1122 elem | s_lo 4*1122 | s_w 16*72 | s_pool 4*196*16 int | bias
#define C1_SMEM 70496
__global__ void __launch_bounds__(512) k_conv1(const float* __restrict__ x,
                                               const float* __restrict__ w1,
                                               const float* __restrict__ b1) {
    extern __shared__ char smem[];
    __nv_bfloat16* s_hi = (__nv_bfloat16*)(smem);            // 4488 elem (4 x 34x33)
    __nv_bfloat16* s_lo = (__nv_bfloat16*)(smem + 8976);     // 4488 elem
    __nv_bfloat16* s_w  = (__nv_bfloat16*)(smem + 17952);    // 16 x 72 elem interleaved
    int*           s_pool = (int*)(smem + 20256);            // 4*196*16
    float*         s_bias = (float*)(smem + 70432);

    const int img0 = blockIdx.x * 4;
    const int tid = threadIdx.x;
    const int warp = tid >> 5;
    const int lane = tid & 31;
    const int gid = lane >> 2;
    const int tg  = lane & 3;

    // zero both planes (17952 B = 4488 u32) + pool
    for (int i = tid; i < 4488; i += 512) ((uint32_t*)smem)[i] = 0u;
    for (int i = tid; i < 12544; i += 512) s_pool[i] = 0;
    if (tid < 16) s_bias[tid] = b1[tid];
    // weights: interleaved [oc][k-pair p], k>=25 -> 0
    if (tid < 256) {
        int oc = tid >> 4, p = tid & 15;
        int k0 = 2 * p, k1 = 2 * p + 1;
        float v0 = (k0 < 25) ? w1[oc * 25 + k0] : 0.f;
        float v1 = (k1 < 25) ? w1[oc * 25 + k1] : 0.f;
        *reinterpret_cast<uint2*>(s_w + oc * 72 + p * 4) = pack4(v0, v1);
    }
    __syncthreads();
    // input split into hi/lo planes (ring offset +2,+2; plane 34 rows x 33 cols)
    for (int i = tid; i < 3136; i += 512) {
        int img = i / 784, px = i - img * 784;
        int iy = px / 28, ix = px - iy * 28;
        __nv_bfloat16 h, l;
        bf16split(x[(img0 + img) * 784 + px], h, l);
        int d = img * 1122 + (iy + 2) * 33 + (ix + 2);
        s_hi[d] = h; s_lo[d] = l;
    }
    __syncthreads();

    // hoist B fragments: [nt][ks][2]
    uint32_t bh[2][2][2], bl[2][2][2];
#pragma unroll
    for (int nt = 0; nt < 2; nt++) {
        int base = (nt * 8 + gid) * 72 + tg * 4;
        uint2 w00 = lds_u64(s_w, base);
        uint2 w01 = lds_u64(s_w, base + 16);
        uint2 w10 = lds_u64(s_w, base + 32);
        uint2 w11 = lds_u64(s_w, base + 48);
        bh[nt][0][0] = w00.x; bl[nt][0][0] = w00.y;
        bh[nt][0][1] = w01.x; bl[nt][0][1] = w01.y;
        bh[nt][1][0] = w10.x; bl[nt][1][0] = w10.y;
        bh[nt][1][1] = w11.x; bl[nt][1][1] = w11.y;
    }

    // per-thread k offsets (k up to 31 -> garbage reads, masked by zero B)
    int doff[8];
    {
        int kk[8] = {2 * tg, 2 * tg + 1, 2 * tg + 8, 2 * tg + 9,
                     2 * tg + 16, 2 * tg + 17, 2 * tg + 24, 2 * tg + 25};
#pragma unroll
        for (int j = 0; j < 8; j++) {
            int ky = kk[j] / 5, kx = kk[j] - ky * 5;
            doff[j] = ky * 33 + kx;
        }
    }

#pragma unroll 1
    for (int ti = 0; ti < 13; ti++) {
        int t = warp + 16 * ti;
        if (t < 196) {
            int img = t / 49;
            int pxb = (t - img * 49) * 16;
            int px0 = pxb + gid, px1 = px0 + 8;
            int y0 = px0 / 28, x0c = px0 - y0 * 28;
            int y1 = px1 / 28, x1c = px1 - y1 * 28;
            int ab0 = img * 1122 + y0 * 33 + x0c;
            int ab1 = img * 1122 + y1 * 33 + x1c;

            uint32_t h0[8], h1[8], l0v[8], l1v[8];
#pragma unroll
            for (int j = 0; j < 8; j++) {
                h0[j] = lds_u16(s_hi, ab0 + doff[j]);
                h1[j] = lds_u16(s_hi, ab1 + doff[j]);
                l0v[j] = lds_u16(s_lo, ab0 + doff[j]);
                l1v[j] = lds_u16(s_lo, ab1 + doff[j]);
            }
            uint32_t A0 = pk(h0[0], h0[1]), A1 = pk(h1[0], h1[1]);
            uint32_t A2 = pk(h0[2], h0[3]), A3 = pk(h1[2], h1[3]);
            uint32_t A4 = pk(h0[4], h0[5]), A5 = pk(h1[4], h1[5]);
            uint32_t A6 = pk(h0[6], h0[7]), A7 = pk(h1[6], h1[7]);
            uint32_t L0 = pk(l0v[0], l0v[1]), L1 = pk(l1v[0], l1v[1]);
            uint32_t L2 = pk(l0v[2], l0v[3]), L3 = pk(l1v[2], l1v[3]);
            uint32_t L4 = pk(l0v[4], l0v[5]), L5 = pk(l1v[4], l1v[5]);
            uint32_t L6 = pk(l0v[6], l0v[7]), L7 = pk(l1v[6], l1v[7]);

            float acc[2][4] = {{0.f, 0.f, 0.f, 0.f}, {0.f, 0.f, 0.f, 0.f}};
#pragma unroll
            for (int nt = 0; nt < 2; nt++) {
                mma_bf16(acc[nt], A0, A1, A2, A3, bh[nt][0][0], bh[nt][0][1]);
                mma_bf16(acc[nt], A4, A5, A6, A7, bh[nt][1][0], bh[nt][1][1]);
                mma_bf16(acc[nt], A0, A1, A2, A3, bl[nt][0][0], bl[nt][0][1]);
                mma_bf16(acc[nt], A4, A5, A6, A7, bl[nt][1][0], bl[nt][1][1]);
                mma_bf16(acc[nt], L0, L1, L2, L3, bh[nt][0][0], bh[nt][0][1]);
                mma_bf16(acc[nt], L4, L5, L6, L7, bh[nt][1][0], bh[nt][1][1]);
            }

            // epilogue: bias+relu, x-pair shfl reduce, atomicMax pool
            int sp0 = (y0 >> 1) * 14 + (x0c >> 1);
            int sp1 = (y1 >> 1) * 14 + (x1c >> 1);
#pragma unroll
            for (int nt = 0; nt < 2; nt++) {
                int c = nt * 8 + tg * 2;
                float bb0 = s_bias[c], bb1 = s_bias[c + 1];
                float v0 = fmaxf(acc[nt][0] + bb0, 0.f);
                float v1 = fmaxf(acc[nt][1] + bb1, 0.f);
                float v2 = fmaxf(acc[nt][2] + bb0, 0.f);
                float v3 = fmaxf(acc[nt][3] + bb1, 0.f);
                float p0 = __shfl_xor_sync(0xffffffffu, v0, 4);
                float p1 = __shfl_xor_sync(0xffffffffu, v1, 4);
                float p2 = __shfl_xor_sync(0xffffffffu, v2, 4);
                float p3 = __shfl_xor_sync(0xffffffffu, v3, 4);
                if ((gid & 1) == 0) {
                    atomicMax(&s_pool[img * 3136 + sp0 * 16 + c], __float_as_int(fmaxf(v0, p0)));
                    atomicMax(&s_pool[img * 3136 + sp0 * 16 + c + 1], __float_as_int(fmaxf(v1, p1)));
                    atomicMax(&s_pool[img * 3136 + sp1 * 16 + c], __float_as_int(fmaxf(v2, p2)));
                    atomicMax(&s_pool[img * 3136 + sp1 * 16 + c + 1], __float_as_int(fmaxf(v3, p3)));
                }
            }
        }
    }
    __syncthreads();
    // write interleaved g_a1
    for (int i = tid; i < 6272; i += 512) {
        int img = i / 1568, rr = i - img * 1568;
        int sp = rr >> 3, p = rr & 7;
        float v0 = __int_as_float(s_pool[img * 3136 + sp * 16 + 2 * p]);
        float v1 = __int_as_float(s_pool[img * 3136 + sp * 16 + 2 * p + 1]);
        *reinterpret_cast<uint2*>(g_a1 + ((img0 + img) * 196 + sp) * 32 + p * 4) = pack4(v0, v1);
    }
}

// ---------------- conv2 (16->32): 4 img/block, 512 thr, cp.async fills ----------------
#define C2_SMEM 201984
__global__ void __launch_bounds__(512) k_conv2(const float* __restrict__ b2) {
    extern __shared__ char smem[];
    __nv_bfloat16* s_in = (__nv_bfloat16*)(smem);               // 62208 elem
    __nv_bfloat16* s_w  = (__nv_bfloat16*)(smem + 124416);      // 26112 elem
    int*           s_pool = (int*)(smem + 176640);              // 6272 int
    float*         s_bias = (float*)(smem + 201728);
    int*           s_lut  = (int*)(smem + 201856);              // 25

    const int img0 = blockIdx.x * 4;
    const int tid = threadIdx.x;
    const int warp = tid >> 5;
    const int lane = tid & 31;
    const int gid = lane >> 2;
    const int tg  = lane & 3;
    const int kq  = tg * 4;

    uint4 z4 = {0, 0, 0, 0};
    for (int i = tid; i < 7776; i += 512) ((uint4*)s_in)[i] = z4;
    for (int i = tid; i < 6272; i += 512) s_pool[i] = 0;
    if (tid < 32) s_bias[tid] = b2[tid];
    if (tid < 25) { int dy = tid / 5, dx = tid - dy * 5; s_lut[tid] = (dy * 18 + dx) * 48; }
    __syncthreads();
    for (int i = tid; i < 3200; i += 512) {
        int oc = i / 100, r = i - oc * 100;
        cp16(s_w + oc * 816 + r * 8, g_w2i + oc * 800 + r * 8);
    }
    for (int i = tid; i < 3136; i += 512) {
        int img = i / 784, r = i - img * 784;
        int px = r >> 2, q = r & 3;
        int y = px / 14, xx = px - y * 14;
        cp16(s_in + img * 15552 + ((y + 2) * 18 + (xx + 2)) * 48 + q * 8,
             g_a1 + ((img0 + img) * 196 + px) * 32 + q * 8);
    }
    CP_COMMIT();
    CP_WAIT(0);
    __syncthreads();

    int aoff0[4], aoff1[4];
#pragma unroll
    for (int ti = 0; ti < 4; ti++) {
        int t = warp + 16 * ti;
        if (t < 49) {
            int r0 = t * 16 + gid, r1 = r0 + 8;
            int i0 = r0 / 196, p0 = r0 - i0 * 196;
            int i1 = r1 / 196, p1 = r1 - i1 * 196;
            int y0 = p0 / 14, x0 = p0 - y0 * 14;
            int y1 = p1 / 14, x1 = p1 - y1 * 14;
            aoff0[ti] = i0 * 15552 + (y0 * 18 + x0) * 48 + kq;
            aoff1[ti] = i1 * 15552 + (y1 * 18 + x1) * 48 + kq;
        }
    }

    float acc[4][4][4];
#pragma unroll
    for (int ti = 0; ti < 4; ti++)
#pragma unroll
        for (int nt = 0; nt < 4; nt++)
#pragma unroll
            for (int j = 0; j < 4; j++) acc[ti][nt][j] = 0.f;

    int wrb[4];
#pragma unroll
    for (int nt = 0; nt < 4; nt++) wrb[nt] = (nt * 8 + gid) * 816 + kq;

#pragma unroll 1
    for (int off = 0; off < 25; off++) {
        const int dpix = s_lut[off];
        const int wofs = off * 32;
        uint32_t bh0[4], bh1[4], bl0[4], bl1[4];
#pragma unroll
        for (int nt = 0; nt < 4; nt++) {
            uint2 w0 = lds_u64(s_w, wrb[nt] + wofs);
            uint2 w1 = lds_u64(s_w, wrb[nt] + wofs + 16);
            bh0[nt] = w0.x; bl0[nt] = w0.y;
            bh1[nt] = w1.x; bl1[nt] = w1.y;
        }
#pragma unroll
        for (int ti = 0; ti < 4; ti++) {
            int t = warp + 16 * ti;
            if (t < 49) {
                int o0 = aoff0[ti] + dpix;
                int o1 = aoff1[ti] + dpix;
                uint2 a00 = lds_u64(s_in, o0);
                uint2 a01 = lds_u64(s_in, o1);
                uint2 a02 = lds_u64(s_in, o0 + 16);
                uint2 a03 = lds_u64(s_in, o1 + 16);
#pragma unroll
                for (int nt = 0; nt < 4; nt++)
                    mma_bf16(acc[ti][nt], a00.x, a01.x, a02.x, a03.x, bh0[nt], bh1[nt]);
#pragma unroll
                for (int nt = 0; nt < 4; nt++)
                    mma_bf16(acc[ti][nt], a00.x, a01.x, a02.x, a03.x, bl0[nt], bl1[nt]);
#pragma unroll
                for (int nt = 0; nt < 4; nt++)
                    mma_bf16(acc[ti][nt], a00.y, a01.y, a02.y, a03.y, bh0[nt], bh1[nt]);
            }
        }
    }

    // epilogue: bias+relu, x-pair shfl reduce, atomicMax pool (halved)
#pragma unroll
    for (int ti = 0; ti < 4; ti++) {
        int t = warp + 16 * ti;
        if (t < 49) {
            int r0 = t * 16 + gid, r1 = r0 + 8;
            int i0 = r0 / 196, p0 = r0 - i0 * 196;
            int i1 = r1 / 196, p1 = r1 - i1 * 196;
            int y0 = p0 / 14, x0 = p0 - y0 * 14;
            int y1 = p1 / 14, x1 = p1 - y1 * 14;
            int pi0 = i0 * 1568 + ((y0 >> 1) * 7 + (x0 >> 1)) * 32;
            int pi1 = i1 * 1568 + ((y1 >> 1) * 7 + (x1 >> 1)) * 32;
#pragma unroll
            for (int nt = 0; nt < 4; nt++) {
                int col = nt * 8 + tg * 2;
                float bb0 = s_bias[col], bb1 = s_bias[col + 1];
                float v0 = fmaxf(acc[ti][nt][0] + bb0, 0.f);
                float v1 = fmaxf(acc[ti][nt][1] + bb1, 0.f);
                float v2 = fmaxf(acc[ti][nt][2] + bb0, 0.f);
                float v3 = fmaxf(acc[ti][nt][3] + bb1, 0.f);
                float q0 = __shfl_xor_sync(0xffffffffu, v0, 4);
                float q1 = __shfl_xor_sync(0xffffffffu, v1, 4);
                float q2 = __shfl_xor_sync(0xffffffffu, v2, 4);
                float q3 = __shfl_xor_sync(0xffffffffu, v3, 4);
                if ((gid & 1) == 0) {
                    atomicMax(&s_pool[pi0 + col], __float_as_int(fmaxf(v0, q0)));
                    atomicMax(&s_pool[pi0 + col + 1], __float_as_int(fmaxf(v1, q1)));
                    atomicMax(&s_pool[pi1 + col], __float_as_int(fmaxf(v2, q2)));
                    atomicMax(&s_pool[pi1 + col + 1], __float_as_int(fmaxf(v3, q3)));
                }
            }
        }
    }
    __syncthreads();
    for (int i = tid; i < 3136; i += 512) {
        int img = i / 784, r = i - img * 784;
        int px = r >> 4, p = r & 15;
        float v0 = __int_as_float(s_pool[img * 1568 + px * 32 + 2 * p]);
        float v1 = __int_as_float(s_pool[img * 1568 + px * 32 + 2 * p + 1]);
        *reinterpret_cast<uint2*>(g_a2 + ((img0 + img) * 49 + px) * 64 + p * 4) = pack4(v0, v1);
    }
}

// ---------------- conv3 (32->64): 5 img/block, 512 thr, cp.async fills ----------------
#define C3_SMEM 210720
__global__ void __launch_bounds__(512) k_conv3(const float* __restrict__ b3) {
    extern __shared__ char smem[];
    __nv_bfloat16* s_in = (__nv_bfloat16*)(smem);               // 48400 elem
    __nv_bfloat16* s_w  = (__nv_bfloat16*)(smem + 96800);       // 51712 elem
    int*           s_pool = (int*)(smem + 200224);              // 2560 int
    float*         s_bias = (float*)(smem + 210464);
    int*           s_lut  = (int*)(smem + 210592);              // 25

    const int img0 = blockIdx.x * 5;
    const int g = blockIdx.y;
    const int tid = threadIdx.x;
    const int warp = tid >> 5;
    const int lane = tid & 31;
    const int gid = lane >> 2;
    const int tg  = lane & 3;
    const int kq  = tg * 4;

    uint4 z4 = {0, 0, 0, 0};
    for (int i = tid; i < 6050; i += 512) ((uint4*)s_in)[i] = z4;
    for (int i = tid; i < 2560; i += 512) s_pool[i] = 0;
    if (tid < 32) s_bias[tid] = b3[g * 32 + tid];
    if (tid < 25) { int dy = tid / 5, dx = tid - dy * 5; s_lut[tid] = (dy * 11 + dx) * 80; }
    __syncthreads();
    const __nv_bfloat16* wg = g_w3i + g * 32 * 1600;
    for (int i = tid; i < 6400; i += 512) {
        int ocl = i / 200, r = i - ocl * 200;
        cp16(s_w + ocl * 1616 + r * 8, wg + ocl * 1600 + r * 8);
    }
    for (int i = tid; i < 1960; i += 512) {
        int img = i / 392, r = i - img * 392;
        if (img0 + img < BATCH) {
            int px = r >> 3, q = r & 7;
            int y = px / 7, xx = px - y * 7;
            cp16(s_in + img * 9680 + ((y + 2) * 11 + (xx + 2)) * 80 + q * 8,
                 g_a2 + ((img0 + img) * 49 + px) * 64 + q * 8);
        }
    }
    CP_COMMIT();
    CP_WAIT(0);
    __syncthreads();

    int r0 = warp * 16 + gid, r1 = r0 + 8;
    int rc0 = r0 < 244 ? r0 : 244;
    int rc1 = r1 < 244 ? r1 : 244;
    int i0 = rc0 / 49, p0 = rc0 - i0 * 49;
    int i1 = rc1 / 49, p1 = rc1 - i1 * 49;
    int y0 = p0 / 7, x0 = p0 - y0 * 7;
    int y1 = p1 / 7, x1 = p1 - y1 * 7;
    const int aoff0 = i0 * 9680 + (y0 * 11 + x0) * 80 + kq;
    const int aoff1 = i1 * 9680 + (y1 * 11 + x1) * 80 + kq;

    float acc[4][4];
#pragma unroll
    for (int nt = 0; nt < 4; nt++)
#pragma unroll
        for (int j = 0; j < 4; j++) acc[nt][j] = 0.f;

    int wrb[4];
#pragma unroll
    for (int nt = 0; nt < 4; nt++) wrb[nt] = (nt * 8 + gid) * 1616 + kq;

#pragma unroll 1
    for (int s = 0; s < 50; s++) {
        const int off = s >> 1;
        const int iche = (s & 1) << 5;
        const int dpix = s_lut[off] + iche;
        const int wofs = off * 64 + iche;
        uint32_t bh0[4], bh1[4], bl0[4], bl1[4];
#pragma unroll
        for (int nt = 0; nt < 4; nt++) {
            uint2 w0 = lds_u64(s_w, wrb[nt] + wofs);
            uint2 w1 = lds_u64(s_w, wrb[nt] + wofs + 16);
            bh0[nt] = w0.x; bl0[nt] = w0.y;
            bh1[nt] = w1.x; bl1[nt] = w1.y;
        }
        int o0 = aoff0 + dpix;
        int o1 = aoff1 + dpix;
        uint2 a00 = lds_u64(s_in, o0);
        uint2 a01 = lds_u64(s_in, o1);
        uint2 a02 = lds_u64(s_in, o0 + 16);
        uint2 a03 = lds_u64(s_in, o1 + 16);
#pragma unroll
        for (int nt = 0; nt < 4; nt++)
            mma_bf16(acc[nt], a00.x, a01.x, a02.x, a03.x, bh0[nt], bh1[nt]);
#pragma unroll
        for (int nt = 0; nt < 4; nt++)
            mma_bf16(acc[nt], a00.x, a01.x, a02.x, a03.x, bl0[nt], bl1[nt]);
#pragma unroll
        for (int nt = 0; nt < 4; nt++)
            mma_bf16(acc[nt], a00.y, a01.y, a02.y, a03.y, bh0[nt], bh1[nt]);
    }

    {
        bool v0 = (r0 < 245) && (img0 + i0 < BATCH);
        bool v1 = (r1 < 245) && (img0 + i1 < BATCH);
        int pi0 = i0 * 512 + (((y0 + 1) >> 1) * 4 + ((x0 + 1) >> 1)) * 32;
        int pi1 = i1 * 512 + (((y1 + 1) >> 1) * 4 + ((x1 + 1) >> 1)) * 32;
#pragma unroll
        for (int nt = 0; nt < 4; nt++) {
            int col = nt * 8 + tg * 2;
            float bb0 = s_bias[col], bb1 = s_bias[col + 1];
            if (v0) {
                atomicMax(&s_pool[pi0 + col], __float_as_int(fmaxf(acc[nt][0] + bb0, 0.f)));
                atomicMax(&s_pool[pi0 + col + 1], __float_as_int(fmaxf(acc[nt][1] + bb1, 0.f)));
            }
            if (v1) {
                atomicMax(&s_pool[pi1 + col], __float_as_int(fmaxf(acc[nt][2] + bb0, 0.f)));
                atomicMax(&s_pool[pi1 + col + 1], __float_as_int(fmaxf(acc[nt][3] + bb1, 0.f)));
            }
        }
    }
    __syncthreads();
    for (int i = tid; i < 1280; i += 512) {
        int img = i >> 8, r = i & 255;
        if (img0 + img < BATCH) {
            int ocl = r >> 3, pp = r & 7;
            float v0 = __int_as_float(s_pool[img * 512 + (2 * pp) * 32 + ocl]);
            float v1 = __int_as_float(s_pool[img * 512 + (2 * pp + 1) * 32 + ocl]);
            int gp = (g * 32 + ocl) * 8 + pp;
            *reinterpret_cast<uint2*>(g_a3 + (img0 + img) * 2048 + gp * 4) = pack4(v0, v1);
        }
    }
}

// ---------------- fc1 via bf16x3 MMA, cp.async double-buffered ----------------
#define FC1_STRIDE 144
#define FC1_STAGE (128 * FC1_STRIDE)
#define FC1_SMEM (4 * FC1_STAGE * 2)
__global__ void __launch_bounds__(256) k_fc1(const float* __restrict__ bias) {
    extern __shared__ char smem[];
    __nv_bfloat16* s_base = (__nv_bfloat16*)smem;
    const int tid = threadIdx.x;
    const int warp = tid >> 5, lane = tid & 31;
    const int wm = warp >> 1, wn = warp & 1;
    const int m0 = blockIdx.y * 128, n0 = blockIdx.x * 128;
    const int gid = lane >> 2, tg = lane & 3;
    const int kq = tg * 4;

    float acc[2][8][4];
#pragma unroll
    for (int mt = 0; mt < 2; mt++)
#pragma unroll
        for (int nt = 0; nt < 8; nt++)
#pragma unroll
            for (int j = 0; j < 4; j++) acc[mt][nt][j] = 0.f;

    auto load_stage = [&](int stage, int k0e) {
        __nv_bfloat16* s_a = s_base + stage * 2 * FC1_STAGE;
        __nv_bfloat16* s_b = s_a + FC1_STAGE;
        for (int i = tid; i < 4096; i += 256) {
            int j = i & 2047;
            int row = j >> 4, q = j & 15;
            int dst = row * FC1_STRIDE + q * 8;
            if (i < 2048)
                cp16(s_a + dst, g_a3 + (m0 + row) * 2048 + k0e + q * 8);
            else
                cp16(s_b + dst, g_fw1 + (n0 + row) * 2048 + k0e + q * 8);
        }
        CP_COMMIT();
    };

    load_stage(0, 0);

#pragma unroll 1
    for (int k = 0; k < 16; k++) {
        if (k < 15) load_stage((k + 1) & 1, (k + 1) * 128);
        if (k < 15) { CP_WAIT(1); } else { CP_WAIT(0); }
        __syncthreads();
        __nv_bfloat16* s_a = s_base + (k & 1) * 2 * FC1_STAGE;
        __nv_bfloat16* s_b = s_a + FC1_STAGE;
#pragma unroll
        for (int ks = 0; ks < 4; ks++) {
            int kb = ks * 32 + kq;
            uint32_t ah[2][4], al[2][4];
#pragma unroll
            for (int mt = 0; mt < 2; mt++) {
                int base = (wm * 32 + mt * 16 + gid) * FC1_STRIDE + kb;
                uint2 q0 = lds_u64(s_a, base);
                uint2 q1 = lds_u64(s_a, base + 8 * FC1_STRIDE);
                uint2 q2 = lds_u64(s_a, base + 16);
                uint2 q3 = lds_u64(s_a, base + 8 * FC1_STRIDE + 16);
                ah[mt][0] = q0.x; al[mt][0] = q0.y;
                ah[mt][1] = q1.x; al[mt][1] = q1.y;
                ah[mt][2] = q2.x; al[mt][2] = q2.y;
                ah[mt][3] = q3.x; al[mt][3] = q3.y;
            }
            uint32_t bh[8][2], bl[8][2];
#pragma unroll
            for (int nt = 0; nt < 8; nt++) {
                int base = (wn * 64 + nt * 8 + gid) * FC1_STRIDE + kb;
                uint2 w0 = lds_u64(s_b, base);
                uint2 w1 = lds_u64(s_b, base + 16);
                bh[nt][0] = w0.x; bl[nt][0] = w0.y;
                bh[nt][1] = w1.x; bl[nt][1] = w1.y;
            }
#pragma unroll
            for (int mt = 0; mt < 2; mt++) {
#pragma unroll
                for (int nt = 0; nt < 8; nt++)
                    mma_bf16(acc[mt][nt], ah[mt][0], ah[mt][1], ah[mt][2], ah[mt][3], bh[nt][0], bh[nt][1]);
#pragma unroll
                for (int nt = 0; nt < 8; nt++)
                    mma_bf16(acc[mt][nt], ah[mt][0], ah[mt][1], ah[mt][2], ah[mt][3], bl[nt][0], bl[nt][1]);
#pragma unroll
                for (int nt = 0; nt < 8; nt++)
                    mma_bf16(acc[mt][nt], al[mt][0], al[mt][1], al[mt][2], al[mt][3], bh[nt][0], bh[nt][1]);
            }
        }
        __syncthreads();
    }
#pragma unroll
    for (int mt = 0; mt < 2; mt++) {
        int r = m0 + wm * 32 + mt * 16 + gid;
#pragma unroll
        for (int nt = 0; nt < 8; nt++) {
            int c = n0 + wn * 64 + nt * 8 + tg * 2;
            float b0 = bias[c], b1 = bias[c + 1];
            g_a4[r * 256 + c]           = fmaxf(acc[mt][nt][0] + b0, 0.f);
            g_a4[r * 256 + c + 1]       = fmaxf(acc[mt][nt][1] + b1, 0.f);
            g_a4[(r + 8) * 256 + c]     = fmaxf(acc[mt][nt][2] + b0, 0.f);
            g_a4[(r + 8) * 256 + c + 1] = fmaxf(acc[mt][nt][3] + b1, 0.f);
        }
    }
}

// ---------------- fc2 + log_softmax ----------------
__global__ void __launch_bounds__(256) k_fc2(const float* __restrict__ W,
                                             const float* __restrict__ bias,
                                             float* __restrict__ out) {
    __shared__ float s_w[2560];
    __shared__ float s_b[10];
    const int tid = threadIdx.x;
    for (int i = tid; i < 2560; i += 256) s_w[i] = W[i];
    if (tid < 10) s_b[tid] = bias[tid];
    __syncthreads();

    const int warp = tid >> 5, lane = tid & 31;
    const int row = blockIdx.x * 8 + warp;
    float hv[8];
    const float* hp = g_a4 + row * 256 + lane;
#pragma unroll
    for (int j = 0; j < 8; j++) hv[j] = hp[j * 32];

    float acc[10];
#pragma unroll
    for (int o = 0; o < 10; o++) acc[o] = 0.f;
#pragma unroll
    for (int j = 0; j < 8; j++) {
#pragma unroll
        for (int o = 0; o < 10; o++)
            acc[o] += hv[j] * s_w[o * 256 + lane + j * 32];
    }
#pragma unroll
    for (int o = 0; o < 10; o++) {
#pragma unroll
        for (int off = 16; off > 0; off >>= 1)
            acc[o] += __shfl_xor_sync(0xffffffffu, acc[o], off);
    }
    if (lane == 0) {
        float l[10], m = -1e30f;
#pragma unroll
        for (int o = 0; o < 10; o++) { l[o] = acc[o] + s_b[o]; m = fmaxf(m, l[o]); }
        float s = 0.f;
#pragma unroll
        for (int o = 0; o < 10; o++) s += expf(l[o] - m);
        float ls = logf(s);
        float* op = out + row * 10;
#pragma unroll
        for (int o = 0; o < 10; o++) op[o] = l[o] - m - ls;
    }
}

extern "C" void kernel_launch(void* const* d_in, const int* in_sizes, int n_in,
                              void* d_out, int out_size) {
    const float* x   = (const float*)d_in[0];
    const float* w1  = (const float*)d_in[1];
    const float* b1  = (const float*)d_in[2];
    const float* w2  = (const float*)d_in[3];
    const float* b2  = (const float*)d_in[4];
    const float* w3  = (const float*)d_in[5];
    const float* b3  = (const float*)d_in[6];
    const float* fw1 = (const float*)d_in[7];
    const float* fb1 = (const float*)d_in[8];
    const float* fw2 = (const float*)d_in[9];
    const float* fb2 = (const float*)d_in[10];
    float* out = (float*)d_out;

    cudaFuncSetAttribute(k_conv1, cudaFuncAttributeMaxDynamicSharedMemorySize, C1_SMEM);
    cudaFuncSetAttribute(k_conv2, cudaFuncAttributeMaxDynamicSharedMemorySize, C2_SMEM);
    cudaFuncSetAttribute(k_conv3, cudaFuncAttributeMaxDynamicSharedMemorySize, C3_SMEM);
    cudaFuncSetAttribute(k_fc1,   cudaFuncAttributeMaxDynamicSharedMemorySize, FC1_SMEM);

    k_prep_fc1<<<512, 256>>>(fw1);
    k_prep_w2<<<25, 256>>>(w2);
    k_prep_w3<<<100, 256>>>(w3);
    k_conv1<<<BATCH / 4, 512, C1_SMEM>>>(x, w1, b1);
    k_conv2<<<BATCH / 4, 512, C2_SMEM>>>(b2);
    k_conv3<<<dim3((BATCH + 4) / 5, 2), 512, C3_SMEM>>>(b3);
    k_fc1<<<dim3(2, BATCH / 128), 256, FC1_SMEM>>>(fb1);
    k_fc2<<<BATCH / 8, 256>>>(fw2, fb2, out);
}